// round 4
// baseline (speedup 1.0000x reference)
#include <cuda_runtime.h>
#include <cstdint>

#define NMAX 50000
#define EMAX 800000
#define FDIM 128
#define CDIM 40

// ---------------- device scratch (static allocation; no cudaMalloc) ----------
__device__ float g_xw [NMAX * FDIM];   // GEMM output of current layer
__device__ float g_h  [NMAX * FDIM];   // aggregated / activated hidden state
__device__ float g_xw3[NMAX * CDIM];   // layer-3 GEMM output
__device__ float g_deg [NMAX];
__device__ float g_dinv[NMAX];
__device__ int   g_src [EMAX];
__device__ int   g_dst [EMAX];
__device__ float g_norm[EMAX];
__device__ float g_sum  [FDIM];
__device__ float g_sumsq[FDIM];
__device__ float g_scale[FDIM];
__device__ float g_shift[FDIM];

// ---------------- graph preprocessing ----------------------------------------
// edge_index is int32: JAX's default jax_enable_x64=False downcasts the
// jnp.int64 request to int32. Reading it as int64 produced garbage addresses
// (the InvalidAddressSpace trap of rounds 1-2).
__global__ void k_init_deg(int N) {
    int i = blockIdx.x * blockDim.x + threadIdx.x;
    if (i < N) g_deg[i] = 1.0f;               // self-loop weight
}

__global__ void k_deg_accum(const int* __restrict__ ei,
                            const float* __restrict__ ew, int E, int N) {
    int e = blockIdx.x * blockDim.x + threadIdx.x;
    if (e >= E) return;
    int d = ei[E + e];
    if ((unsigned)d < (unsigned)N) atomicAdd(&g_deg[d], ew[e]);
}

__global__ void k_dinv(int N) {
    int i = blockIdx.x * blockDim.x + threadIdx.x;
    if (i < N) g_dinv[i] = rsqrtf(g_deg[i]);   // deg >= 1 always
}

__global__ void k_edge_prep(const int* __restrict__ ei,
                            const float* __restrict__ ew, int E, int N) {
    int e = blockIdx.x * blockDim.x + threadIdx.x;
    if (e >= E) return;
    int s = ei[e];
    int d = ei[E + e];
    if ((unsigned)s >= (unsigned)N) s = 0;
    if ((unsigned)d >= (unsigned)N) d = 0;
    g_src[e]  = s;
    g_dst[e]  = d;
    g_norm[e] = g_dinv[s] * ew[e] * g_dinv[d];
}

// ---------------- SGEMM: [M,128] @ [128,128] ---------------------------------
// aext_sel: 0 -> read A from external pointer (layer 1 input x); 1 -> read g_h.
// Output always g_xw.
__global__ __launch_bounds__(256) void k_gemm128(const float* __restrict__ Aext,
                                                 int aext_sel,
                                                 const float* __restrict__ B,
                                                 int M) {
    const float* __restrict__ A = aext_sel ? (const float*)g_h : Aext;
    __shared__ float As[16][128];   // transposed: [k][row]
    __shared__ float Bs[16][128];   // [k][col]
    const int tid  = threadIdx.x;
    const int tx   = tid & 15;      // col group (8 cols)
    const int ty   = tid >> 4;      // row group (8 rows)
    const int row0 = blockIdx.x * 128;
    const int a_row = tid >> 1;
    const int a_k4  = (tid & 1) * 8;
    const int b_k   = tid >> 4;
    const int b_n   = (tid & 15) * 8;

    float acc[8][8];
#pragma unroll
    for (int i = 0; i < 8; i++)
#pragma unroll
        for (int j = 0; j < 8; j++) acc[i][j] = 0.f;

#pragma unroll 1
    for (int k0 = 0; k0 < 128; k0 += 16) {
        int grow = row0 + a_row;
        float4 av0 = make_float4(0.f, 0.f, 0.f, 0.f);
        float4 av1 = av0;
        if (grow < M) {
            const float* ap = A + (size_t)grow * 128 + k0 + a_k4;
            av0 = *(const float4*)ap;
            av1 = *(const float4*)(ap + 4);
        }
        As[a_k4 + 0][a_row] = av0.x; As[a_k4 + 1][a_row] = av0.y;
        As[a_k4 + 2][a_row] = av0.z; As[a_k4 + 3][a_row] = av0.w;
        As[a_k4 + 4][a_row] = av1.x; As[a_k4 + 5][a_row] = av1.y;
        As[a_k4 + 6][a_row] = av1.z; As[a_k4 + 7][a_row] = av1.w;

        const float* bp = B + (size_t)(k0 + b_k) * 128 + b_n;
        *(float4*)&Bs[b_k][b_n]     = *(const float4*)bp;
        *(float4*)&Bs[b_k][b_n + 4] = *(const float4*)(bp + 4);
        __syncthreads();

#pragma unroll
        for (int kk = 0; kk < 16; kk++) {
            float ar[8], br[8];
            *(float4*)&ar[0] = *(const float4*)&As[kk][ty * 8];
            *(float4*)&ar[4] = *(const float4*)&As[kk][ty * 8 + 4];
            *(float4*)&br[0] = *(const float4*)&Bs[kk][tx * 8];
            *(float4*)&br[4] = *(const float4*)&Bs[kk][tx * 8 + 4];
#pragma unroll
            for (int i = 0; i < 8; i++)
#pragma unroll
                for (int j = 0; j < 8; j++)
                    acc[i][j] = fmaf(ar[i], br[j], acc[i][j]);
        }
        __syncthreads();
    }

#pragma unroll
    for (int i = 0; i < 8; i++) {
        int r = row0 + ty * 8 + i;
        if (r < M) {
            float4 o0 = make_float4(acc[i][0], acc[i][1], acc[i][2], acc[i][3]);
            float4 o1 = make_float4(acc[i][4], acc[i][5], acc[i][6], acc[i][7]);
            *(float4*)(g_xw + (size_t)r * 128 + tx * 8)     = o0;
            *(float4*)(g_xw + (size_t)r * 128 + tx * 8 + 4) = o1;
        }
    }
}

// ---------------- SGEMM: [M,128] @ [128,40]  (g_h -> g_xw3) -------------------
__global__ __launch_bounds__(256) void k_gemm40(const float* __restrict__ B,
                                                int M) {
    __shared__ float As[16][128];
    __shared__ float Bs[16][40];
    const int tid  = threadIdx.x;
    const int tx   = tid & 7;    // 8 col groups of 5
    const int ty   = tid >> 3;   // 32 row groups of 4
    const int row0 = blockIdx.x * 128;
    const int a_row = tid >> 1;
    const int a_k4  = (tid & 1) * 8;

    float acc[4][5];
#pragma unroll
    for (int i = 0; i < 4; i++)
#pragma unroll
        for (int j = 0; j < 5; j++) acc[i][j] = 0.f;

#pragma unroll 1
    for (int k0 = 0; k0 < 128; k0 += 16) {
        int grow = row0 + a_row;
        float4 av0 = make_float4(0.f, 0.f, 0.f, 0.f);
        float4 av1 = av0;
        if (grow < M) {
            const float* ap = g_h + (size_t)grow * 128 + k0 + a_k4;
            av0 = *(const float4*)ap;
            av1 = *(const float4*)(ap + 4);
        }
        As[a_k4 + 0][a_row] = av0.x; As[a_k4 + 1][a_row] = av0.y;
        As[a_k4 + 2][a_row] = av0.z; As[a_k4 + 3][a_row] = av0.w;
        As[a_k4 + 4][a_row] = av1.x; As[a_k4 + 5][a_row] = av1.y;
        As[a_k4 + 6][a_row] = av1.z; As[a_k4 + 7][a_row] = av1.w;

        for (int i = tid; i < 16 * 40; i += 256) {
            int bk = i / 40, bn = i % 40;
            Bs[bk][bn] = B[(size_t)(k0 + bk) * 40 + bn];
        }
        __syncthreads();

#pragma unroll
        for (int kk = 0; kk < 16; kk++) {
            float ar[4], br[5];
#pragma unroll
            for (int i = 0; i < 4; i++) ar[i] = As[kk][ty * 4 + i];
#pragma unroll
            for (int j = 0; j < 5; j++) br[j] = Bs[kk][tx * 5 + j];
#pragma unroll
            for (int i = 0; i < 4; i++)
#pragma unroll
                for (int j = 0; j < 5; j++)
                    acc[i][j] = fmaf(ar[i], br[j], acc[i][j]);
        }
        __syncthreads();
    }

#pragma unroll
    for (int i = 0; i < 4; i++) {
        int r = row0 + ty * 4 + i;
        if (r < M) {
#pragma unroll
            for (int j = 0; j < 5; j++)
                g_xw3[(size_t)r * 40 + tx * 5 + j] = acc[i][j];
        }
    }
}

// ---------------- aggregation ------------------------------------------------
// g_h[i] = b + dinv[i]^2 * g_xw[i]   (self-loop message + bias)
__global__ void k_init_out128(const float* __restrict__ b, int N) {
    int idx = blockIdx.x * blockDim.x + threadIdx.x;
    if (idx >= N * 32) return;
    int row = idx >> 5, c4 = idx & 31;
    float di = g_dinv[row]; di *= di;
    float4 bv = ((const float4*)b)[c4];
    float4 xv = ((const float4*)g_xw)[idx];
    ((float4*)g_h)[idx] = make_float4(fmaf(di, xv.x, bv.x), fmaf(di, xv.y, bv.y),
                                      fmaf(di, xv.z, bv.z), fmaf(di, xv.w, bv.w));
}

__global__ void k_init_out40(const float* __restrict__ b,
                             float* __restrict__ out, int N) {
    int idx = blockIdx.x * blockDim.x + threadIdx.x;
    if (idx >= N * 10) return;
    int row = idx / 10, c4 = idx % 10;
    float di = g_dinv[row]; di *= di;
    float4 bv = ((const float4*)b)[c4];
    float4 xv = ((const float4*)g_xw3)[idx];
    ((float4*)out)[idx] = make_float4(fmaf(di, xv.x, bv.x), fmaf(di, xv.y, bv.y),
                                      fmaf(di, xv.z, bv.z), fmaf(di, xv.w, bv.w));
}

// one warp per edge: g_h[dst] += norm * g_xw[src]
__global__ void k_scatter128(int E) {
    int t = blockIdx.x * blockDim.x + threadIdx.x;
    int e = t >> 5;
    if (e >= E) return;
    int lane = t & 31;
    // lane 0 loads edge metadata, broadcast to the warp (saves 3 loads/lane)
    int s = 0, d = 0; float nrm = 0.f;
    if (lane == 0) { s = g_src[e]; d = g_dst[e]; nrm = g_norm[e]; }
    s   = __shfl_sync(0xffffffffu, s, 0);
    d   = __shfl_sync(0xffffffffu, d, 0);
    nrm = __shfl_sync(0xffffffffu, nrm, 0);
    float4 v = *(const float4*)(g_xw + (size_t)s * 128 + lane * 4);
    float* p = g_h + (size_t)d * 128 + lane * 4;
    atomicAdd(p + 0, v.x * nrm);
    atomicAdd(p + 1, v.y * nrm);
    atomicAdd(p + 2, v.z * nrm);
    atomicAdd(p + 3, v.w * nrm);
}

// 16 threads per edge, lanes 0..9 active (40 floats = 10 float4)
__global__ void k_scatter40(float* __restrict__ out, int E) {
    int t = blockIdx.x * blockDim.x + threadIdx.x;
    int e = t >> 4;
    int half = t & 15;
    if (e >= E) return;
    int s = 0, d = 0; float nrm = 0.f;
    if (half == 0) { s = g_src[e]; d = g_dst[e]; nrm = g_norm[e]; }
    // broadcast within each 16-thread group
    s   = __shfl_sync(0xffffffffu, s,   (threadIdx.x & 31) & ~15);
    d   = __shfl_sync(0xffffffffu, d,   (threadIdx.x & 31) & ~15);
    nrm = __shfl_sync(0xffffffffu, nrm, (threadIdx.x & 31) & ~15);
    if (half >= 10) return;
    float4 v = *(const float4*)(g_xw3 + (size_t)s * 40 + half * 4);
    float* p = out + (size_t)d * 40 + half * 4;
    atomicAdd(p + 0, v.x * nrm);
    atomicAdd(p + 1, v.y * nrm);
    atomicAdd(p + 2, v.z * nrm);
    atomicAdd(p + 3, v.w * nrm);
}

// ---------------- batch norm + relu (on g_h) ----------------------------------
__global__ void k_bn_zero() {
    int t = threadIdx.x;
    g_sum[t] = 0.f;
    g_sumsq[t] = 0.f;
}

__global__ void k_bn_stats(int N) {
    int col = threadIdx.x;            // 128 threads
    float s = 0.f, s2 = 0.f;
    for (int r = blockIdx.x; r < N; r += gridDim.x) {
        float v = g_h[(size_t)r * 128 + col];
        s += v; s2 += v * v;
    }
    atomicAdd(&g_sum[col], s);
    atomicAdd(&g_sumsq[col], s2);
}

__global__ void k_bn_final(const float* __restrict__ gamma,
                           const float* __restrict__ beta, float invN) {
    int t = threadIdx.x;
    float mean = g_sum[t] * invN;
    float var  = fmaf(-mean, mean, g_sumsq[t] * invN);
    float sc   = gamma[t] * rsqrtf(var + 1e-5f);
    g_scale[t] = sc;
    g_shift[t] = fmaf(-mean, sc, beta[t]);
}

__global__ void k_bn_apply_relu(int N) {
    int idx = blockIdx.x * blockDim.x + threadIdx.x;
    if (idx >= N * 32) return;
    int c4 = idx & 31;
    float4 v  = ((const float4*)g_h)[idx];
    float4 sc = ((const float4*)g_scale)[c4];
    float4 sh = ((const float4*)g_shift)[c4];
    v.x = fmaxf(0.f, fmaf(v.x, sc.x, sh.x));
    v.y = fmaxf(0.f, fmaf(v.y, sc.y, sh.y));
    v.z = fmaxf(0.f, fmaf(v.z, sc.z, sh.z));
    v.w = fmaxf(0.f, fmaf(v.w, sc.w, sh.w));
    ((float4*)g_h)[idx] = v;
}

// ---------------- log_softmax over 40 classes (warp per row) ------------------
__global__ void k_logsoftmax(float* __restrict__ out, int N) {
    int t = blockIdx.x * blockDim.x + threadIdx.x;
    int row = t >> 5, lane = t & 31;
    if (row >= N) return;
    float* p = out + (size_t)row * 40;
    float v1 = p[lane];
    float v2 = (lane < 8) ? p[32 + lane] : 0.f;
    float m = (lane < 8) ? fmaxf(v1, v2) : v1;
#pragma unroll
    for (int o = 16; o > 0; o >>= 1) m = fmaxf(m, __shfl_xor_sync(0xffffffffu, m, o));
    float s = expf(v1 - m) + ((lane < 8) ? expf(v2 - m) : 0.f);
#pragma unroll
    for (int o = 16; o > 0; o >>= 1) s += __shfl_xor_sync(0xffffffffu, s, o);
    float l = m + logf(s);
    p[lane] = v1 - l;
    if (lane < 8) p[32 + lane] = v2 - l;
}

// ---------------- launch -----------------------------------------------------
extern "C" void kernel_launch(void* const* d_in, const int* in_sizes, int n_in,
                              void* d_out, int out_size) {
    const float* x   = (const float*)d_in[0];
    const int*   ei  = (const int*)d_in[1];     // int32 (JAX x64 disabled)
    const float* ew  = (const float*)d_in[2];
    const float* W1  = (const float*)d_in[3];
    const float* b1  = (const float*)d_in[4];
    const float* ga1 = (const float*)d_in[5];
    const float* be1 = (const float*)d_in[6];
    const float* W2  = (const float*)d_in[7];
    const float* b2  = (const float*)d_in[8];
    const float* ga2 = (const float*)d_in[9];
    const float* be2 = (const float*)d_in[10];
    const float* W3  = (const float*)d_in[11];
    const float* b3  = (const float*)d_in[12];
    float* out = (float*)d_out;

    int N = in_sizes[0] / FDIM;
    int E = in_sizes[2];

    const int TB = 256;
    int gbN   = (N + TB - 1) / TB;
    int gbE   = (E + TB - 1) / TB;
    int gbM   = (N + 127) / 128;            // gemm row tiles
    int gbNF  = (N * 32 + TB - 1) / TB;     // N*128/4 float4 elems
    int gbE32 = (int)(((long long)E * 32 + TB - 1) / TB);
    int gbE16 = (int)(((long long)E * 16 + TB - 1) / TB);
    int gbN10 = (N * 10 + TB - 1) / TB;
    int gbN32 = (N * 32 + TB - 1) / TB;     // warp-per-row softmax threads

    // ---- graph normalization precompute ----
    k_init_deg <<<gbN, TB>>>(N);
    k_deg_accum<<<gbE, TB>>>(ei, ew, E, N);
    k_dinv     <<<gbN, TB>>>(N);
    k_edge_prep<<<gbE, TB>>>(ei, ew, E, N);

    // ---- layer 1 ----
    k_gemm128   <<<gbM, 256>>>(x, 0, W1, N);
    k_init_out128<<<gbNF, TB>>>(b1, N);
    k_scatter128<<<gbE32, TB>>>(E);
    k_bn_zero   <<<1, 128>>>();
    k_bn_stats  <<<512, 128>>>(N);
    k_bn_final  <<<1, 128>>>(ga1, be1, 1.0f / (float)N);
    k_bn_apply_relu<<<gbNF, TB>>>(N);

    // ---- layer 2 ----
    k_gemm128   <<<gbM, 256>>>(x, 1, W2, N);
    k_init_out128<<<gbNF, TB>>>(b2, N);
    k_scatter128<<<gbE32, TB>>>(E);
    k_bn_zero   <<<1, 128>>>();
    k_bn_stats  <<<512, 128>>>(N);
    k_bn_final  <<<1, 128>>>(ga2, be2, 1.0f / (float)N);
    k_bn_apply_relu<<<gbNF, TB>>>(N);

    // ---- layer 3 + log_softmax ----
    k_gemm40    <<<gbM, 256>>>(W3, N);
    k_init_out40<<<gbN10, TB>>>(b3, out, N);
    k_scatter40 <<<gbE16, TB>>>(out, E);
    k_logsoftmax<<<gbN32, TB>>>(out, N);
}

// round 5
// speedup vs baseline: 1.6378x; 1.6378x over previous
#include <cuda_runtime.h>
#include <cstdint>

#define NMAX 50000
#define EMAX 800000
#define FDIM 128
#define CDIM 40
#define SCAN_T 1024

// ---------------- device scratch (static allocation; no cudaMalloc) ----------
__device__ float g_xw [NMAX * FDIM];   // GEMM output of current layer
__device__ float g_h  [NMAX * FDIM];   // aggregated / activated hidden state
__device__ float g_xw3[NMAX * CDIM];   // layer-3 GEMM output
__device__ float g_deg [NMAX];
__device__ float g_dinv[NMAX];
__device__ int   g_src [EMAX];
__device__ int   g_dst [EMAX];
__device__ float g_norm[EMAX];
__device__ int   g_cnt   [NMAX];       // in-degree counts
__device__ int   g_rowptr[NMAX + 1];   // CSR row pointers (by dst)
__device__ int   g_cursor[NMAX];       // fill cursors
__device__ int2  g_csr   [EMAX];       // packed {src, bitcast(norm)}
__device__ float g_sum  [FDIM];
__device__ float g_sumsq[FDIM];
__device__ float g_scale[FDIM];
__device__ float g_shift[FDIM];

// ---------------- graph preprocessing ----------------------------------------
// edge_index is int32 (JAX x64 disabled downcasts jnp.int64 -> int32).
__global__ void k_init_deg(int N) {
    int i = blockIdx.x * blockDim.x + threadIdx.x;
    if (i < N) { g_deg[i] = 1.0f; g_cnt[i] = 0; }   // self-loop weight; zero histogram
}

__global__ void k_deg_accum(const int* __restrict__ ei,
                            const float* __restrict__ ew, int E, int N) {
    int e = blockIdx.x * blockDim.x + threadIdx.x;
    if (e >= E) return;
    int d = ei[E + e];
    if ((unsigned)d < (unsigned)N) atomicAdd(&g_deg[d], ew[e]);
}

__global__ void k_dinv(int N) {
    int i = blockIdx.x * blockDim.x + threadIdx.x;
    if (i < N) g_dinv[i] = rsqrtf(g_deg[i]);   // deg >= 1 always
}

__global__ void k_edge_prep(const int* __restrict__ ei,
                            const float* __restrict__ ew, int E, int N) {
    int e = blockIdx.x * blockDim.x + threadIdx.x;
    if (e >= E) return;
    int s = ei[e];
    int d = ei[E + e];
    if ((unsigned)s >= (unsigned)N) s = 0;
    if ((unsigned)d >= (unsigned)N) d = 0;
    g_src[e]  = s;
    g_dst[e]  = d;
    g_norm[e] = g_dinv[s] * ew[e] * g_dinv[d];
    atomicAdd(&g_cnt[d], 1);
}

// single-block exclusive scan over N counts -> rowptr + cursor
__global__ void k_scan(int N) {
    __shared__ int sh[SCAN_T];
    int tid = threadIdx.x;
    int chunk = (N + SCAN_T - 1) / SCAN_T;
    int start = tid * chunk;
    int end   = min(start + chunk, N);
    int sum = 0;
    for (int i = start; i < end; i++) sum += g_cnt[i];
    sh[tid] = sum;
    __syncthreads();
    for (int off = 1; off < SCAN_T; off <<= 1) {
        int v = (tid >= off) ? sh[tid - off] : 0;
        __syncthreads();
        sh[tid] += v;
        __syncthreads();
    }
    int off = sh[tid] - sum;   // exclusive prefix
    for (int i = start; i < end; i++) {
        g_rowptr[i] = off;
        g_cursor[i] = off;
        off += g_cnt[i];
    }
    if (tid == SCAN_T - 1) g_rowptr[N] = off;
}

__global__ void k_csr_fill(int E) {
    int e = blockIdx.x * blockDim.x + threadIdx.x;
    if (e >= E) return;
    int d = g_dst[e];
    int pos = atomicAdd(&g_cursor[d], 1);
    g_csr[pos] = make_int2(g_src[e], __float_as_int(g_norm[e]));
}

// ---------------- SGEMM: [M,128] @ [128,128] ---------------------------------
// aext_sel: 0 -> A = external x; 1 -> A = g_h. Output g_xw.
__global__ __launch_bounds__(256) void k_gemm128(const float* __restrict__ Aext,
                                                 int aext_sel,
                                                 const float* __restrict__ B,
                                                 int M) {
    const float* __restrict__ A = aext_sel ? (const float*)g_h : Aext;
    __shared__ float As[16][128];   // transposed: [k][row]
    __shared__ float Bs[16][128];   // [k][col]
    const int tid  = threadIdx.x;
    const int tx   = tid & 15;
    const int ty   = tid >> 4;
    const int row0 = blockIdx.x * 128;
    const int a_row = tid >> 1;
    const int a_k4  = (tid & 1) * 8;
    const int b_k   = tid >> 4;
    const int b_n   = (tid & 15) * 8;

    float acc[8][8];
#pragma unroll
    for (int i = 0; i < 8; i++)
#pragma unroll
        for (int j = 0; j < 8; j++) acc[i][j] = 0.f;

#pragma unroll 1
    for (int k0 = 0; k0 < 128; k0 += 16) {
        int grow = row0 + a_row;
        float4 av0 = make_float4(0.f, 0.f, 0.f, 0.f);
        float4 av1 = av0;
        if (grow < M) {
            const float* ap = A + (size_t)grow * 128 + k0 + a_k4;
            av0 = *(const float4*)ap;
            av1 = *(const float4*)(ap + 4);
        }
        As[a_k4 + 0][a_row] = av0.x; As[a_k4 + 1][a_row] = av0.y;
        As[a_k4 + 2][a_row] = av0.z; As[a_k4 + 3][a_row] = av0.w;
        As[a_k4 + 4][a_row] = av1.x; As[a_k4 + 5][a_row] = av1.y;
        As[a_k4 + 6][a_row] = av1.z; As[a_k4 + 7][a_row] = av1.w;

        const float* bp = B + (size_t)(k0 + b_k) * 128 + b_n;
        *(float4*)&Bs[b_k][b_n]     = *(const float4*)bp;
        *(float4*)&Bs[b_k][b_n + 4] = *(const float4*)(bp + 4);
        __syncthreads();

#pragma unroll
        for (int kk = 0; kk < 16; kk++) {
            float ar[8], br[8];
            *(float4*)&ar[0] = *(const float4*)&As[kk][ty * 8];
            *(float4*)&ar[4] = *(const float4*)&As[kk][ty * 8 + 4];
            *(float4*)&br[0] = *(const float4*)&Bs[kk][tx * 8];
            *(float4*)&br[4] = *(const float4*)&Bs[kk][tx * 8 + 4];
#pragma unroll
            for (int i = 0; i < 8; i++)
#pragma unroll
                for (int j = 0; j < 8; j++)
                    acc[i][j] = fmaf(ar[i], br[j], acc[i][j]);
        }
        __syncthreads();
    }

#pragma unroll
    for (int i = 0; i < 8; i++) {
        int r = row0 + ty * 8 + i;
        if (r < M) {
            float4 o0 = make_float4(acc[i][0], acc[i][1], acc[i][2], acc[i][3]);
            float4 o1 = make_float4(acc[i][4], acc[i][5], acc[i][6], acc[i][7]);
            *(float4*)(g_xw + (size_t)r * 128 + tx * 8)     = o0;
            *(float4*)(g_xw + (size_t)r * 128 + tx * 8 + 4) = o1;
        }
    }
}

// ---------------- SGEMM: [M,128] @ [128,40]  (g_h -> g_xw3) -------------------
__global__ __launch_bounds__(256) void k_gemm40(const float* __restrict__ B,
                                                int M) {
    __shared__ float As[16][128];
    __shared__ float Bs[16][40];
    const int tid  = threadIdx.x;
    const int tx   = tid & 7;
    const int ty   = tid >> 3;
    const int row0 = blockIdx.x * 128;
    const int a_row = tid >> 1;
    const int a_k4  = (tid & 1) * 8;

    float acc[4][5];
#pragma unroll
    for (int i = 0; i < 4; i++)
#pragma unroll
        for (int j = 0; j < 5; j++) acc[i][j] = 0.f;

#pragma unroll 1
    for (int k0 = 0; k0 < 128; k0 += 16) {
        int grow = row0 + a_row;
        float4 av0 = make_float4(0.f, 0.f, 0.f, 0.f);
        float4 av1 = av0;
        if (grow < M) {
            const float* ap = g_h + (size_t)grow * 128 + k0 + a_k4;
            av0 = *(const float4*)ap;
            av1 = *(const float4*)(ap + 4);
        }
        As[a_k4 + 0][a_row] = av0.x; As[a_k4 + 1][a_row] = av0.y;
        As[a_k4 + 2][a_row] = av0.z; As[a_k4 + 3][a_row] = av0.w;
        As[a_k4 + 4][a_row] = av1.x; As[a_k4 + 5][a_row] = av1.y;
        As[a_k4 + 6][a_row] = av1.z; As[a_k4 + 7][a_row] = av1.w;

        for (int i = tid; i < 16 * 40; i += 256) {
            int bk = i / 40, bn = i % 40;
            Bs[bk][bn] = B[(size_t)(k0 + bk) * 40 + bn];
        }
        __syncthreads();

#pragma unroll
        for (int kk = 0; kk < 16; kk++) {
            float ar[4], br[5];
#pragma unroll
            for (int i = 0; i < 4; i++) ar[i] = As[kk][ty * 4 + i];
#pragma unroll
            for (int j = 0; j < 5; j++) br[j] = Bs[kk][tx * 5 + j];
#pragma unroll
            for (int i = 0; i < 4; i++)
#pragma unroll
                for (int j = 0; j < 5; j++)
                    acc[i][j] = fmaf(ar[i], br[j], acc[i][j]);
        }
        __syncthreads();
    }

#pragma unroll
    for (int i = 0; i < 4; i++) {
        int r = row0 + ty * 4 + i;
        if (r < M) {
#pragma unroll
            for (int j = 0; j < 5; j++)
                g_xw3[(size_t)r * 40 + tx * 5 + j] = acc[i][j];
        }
    }
}

// ---------------- CSR gather aggregation --------------------------------------
// one block (128 threads) per node:
// g_h[n][c] = b[c] + dinv[n]^2 * g_xw[n][c] + sum_j norm_j * g_xw[src_j][c]
__global__ __launch_bounds__(128) void k_gather128(const float* __restrict__ b,
                                                   int N) {
    int n = blockIdx.x;
    int c = threadIdx.x;
    float di = g_dinv[n]; di *= di;
    float acc0 = fmaf(di, g_xw[(size_t)n * 128 + c], b[c]);
    float acc1 = 0.f;
    int j   = g_rowptr[n];
    int end = g_rowptr[n + 1];
    for (; j + 1 < end; j += 2) {
        int2 e0 = g_csr[j];
        int2 e1 = g_csr[j + 1];
        acc0 = fmaf(__int_as_float(e0.y), g_xw[(size_t)e0.x * 128 + c], acc0);
        acc1 = fmaf(__int_as_float(e1.y), g_xw[(size_t)e1.x * 128 + c], acc1);
    }
    if (j < end) {
        int2 e = g_csr[j];
        acc0 = fmaf(__int_as_float(e.y), g_xw[(size_t)e.x * 128 + c], acc0);
    }
    g_h[(size_t)n * 128 + c] = acc0 + acc1;
}

// layer 3: gather + bias + self-loop + log_softmax, one warp per node
__global__ void k_gather40_lsm(const float* __restrict__ b3,
                               float* __restrict__ out, int N) {
    int t = blockIdx.x * blockDim.x + threadIdx.x;
    int n = t >> 5, lane = t & 31;
    if (n >= N) return;
    float di = g_dinv[n]; di *= di;
    const float* xr = g_xw3 + (size_t)n * 40;
    float v1 = fmaf(di, xr[lane], b3[lane]);
    float v2 = (lane < 8) ? fmaf(di, xr[32 + lane], b3[32 + lane]) : 0.f;
    int j   = g_rowptr[n];
    int end = g_rowptr[n + 1];
    for (; j < end; j++) {
        int2 e = g_csr[j];
        float w = __int_as_float(e.y);
        const float* sr = g_xw3 + (size_t)e.x * 40;
        v1 = fmaf(w, sr[lane], v1);
        if (lane < 8) v2 = fmaf(w, sr[32 + lane], v2);
    }
    float m = (lane < 8) ? fmaxf(v1, v2) : v1;
#pragma unroll
    for (int o = 16; o > 0; o >>= 1) m = fmaxf(m, __shfl_xor_sync(0xffffffffu, m, o));
    float s = expf(v1 - m) + ((lane < 8) ? expf(v2 - m) : 0.f);
#pragma unroll
    for (int o = 16; o > 0; o >>= 1) s += __shfl_xor_sync(0xffffffffu, s, o);
    float l = m + logf(s);
    float* p = out + (size_t)n * 40;
    p[lane] = v1 - l;
    if (lane < 8) p[32 + lane] = v2 - l;
}

// ---------------- batch norm + relu (on g_h) ----------------------------------
__global__ void k_bn_zero() {
    int t = threadIdx.x;
    g_sum[t] = 0.f;
    g_sumsq[t] = 0.f;
}

__global__ void k_bn_stats(int N) {
    int col = threadIdx.x;            // 128 threads
    float s = 0.f, s2 = 0.f;
    for (int r = blockIdx.x; r < N; r += gridDim.x) {
        float v = g_h[(size_t)r * 128 + col];
        s += v; s2 += v * v;
    }
    atomicAdd(&g_sum[col], s);
    atomicAdd(&g_sumsq[col], s2);
}

__global__ void k_bn_final(const float* __restrict__ gamma,
                           const float* __restrict__ beta, float invN) {
    int t = threadIdx.x;
    float mean = g_sum[t] * invN;
    float var  = fmaf(-mean, mean, g_sumsq[t] * invN);
    float sc   = gamma[t] * rsqrtf(var + 1e-5f);
    g_scale[t] = sc;
    g_shift[t] = fmaf(-mean, sc, beta[t]);
}

__global__ void k_bn_apply_relu(int N) {
    int idx = blockIdx.x * blockDim.x + threadIdx.x;
    if (idx >= N * 32) return;
    int c4 = idx & 31;
    float4 v  = ((const float4*)g_h)[idx];
    float4 sc = ((const float4*)g_scale)[c4];
    float4 sh = ((const float4*)g_shift)[c4];
    v.x = fmaxf(0.f, fmaf(v.x, sc.x, sh.x));
    v.y = fmaxf(0.f, fmaf(v.y, sc.y, sh.y));
    v.z = fmaxf(0.f, fmaf(v.z, sc.z, sh.z));
    v.w = fmaxf(0.f, fmaf(v.w, sc.w, sh.w));
    ((float4*)g_h)[idx] = v;
}

// ---------------- launch -----------------------------------------------------
extern "C" void kernel_launch(void* const* d_in, const int* in_sizes, int n_in,
                              void* d_out, int out_size) {
    const float* x   = (const float*)d_in[0];
    const int*   ei  = (const int*)d_in[1];     // int32 (JAX x64 disabled)
    const float* ew  = (const float*)d_in[2];
    const float* W1  = (const float*)d_in[3];
    const float* b1  = (const float*)d_in[4];
    const float* ga1 = (const float*)d_in[5];
    const float* be1 = (const float*)d_in[6];
    const float* W2  = (const float*)d_in[7];
    const float* b2  = (const float*)d_in[8];
    const float* ga2 = (const float*)d_in[9];
    const float* be2 = (const float*)d_in[10];
    const float* W3  = (const float*)d_in[11];
    const float* b3  = (const float*)d_in[12];
    float* out = (float*)d_out;

    int N = in_sizes[0] / FDIM;
    int E = in_sizes[2];

    const int TB = 256;
    int gbN  = (N + TB - 1) / TB;
    int gbE  = (E + TB - 1) / TB;
    int gbM  = (N + 127) / 128;
    int gbNF = (N * 32 + TB - 1) / TB;
    int gbNW = (N * 32 + TB - 1) / TB;      // warp-per-node

    // ---- graph preprocessing + CSR build ----
    k_init_deg <<<gbN, TB>>>(N);
    k_deg_accum<<<gbE, TB>>>(ei, ew, E, N);
    k_dinv     <<<gbN, TB>>>(N);
    k_edge_prep<<<gbE, TB>>>(ei, ew, E, N);
    k_scan     <<<1, SCAN_T>>>(N);
    k_csr_fill <<<gbE, TB>>>(E);

    // ---- layer 1 ----
    k_gemm128  <<<gbM, 256>>>(x, 0, W1, N);
    k_gather128<<<N, 128>>>(b1, N);
    k_bn_zero  <<<1, 128>>>();
    k_bn_stats <<<512, 128>>>(N);
    k_bn_final <<<1, 128>>>(ga1, be1, 1.0f / (float)N);
    k_bn_apply_relu<<<gbNF, TB>>>(N);

    // ---- layer 2 ----
    k_gemm128  <<<gbM, 256>>>(x, 1, W2, N);
    k_gather128<<<N, 128>>>(b2, N);
    k_bn_zero  <<<1, 128>>>();
    k_bn_stats <<<512, 128>>>(N);
    k_bn_final <<<1, 128>>>(ga2, be2, 1.0f / (float)N);
    k_bn_apply_relu<<<gbNF, TB>>>(N);

    // ---- layer 3 + log_softmax (fused) ----
    k_gemm40       <<<gbM, 256>>>(W3, N);
    k_gather40_lsm <<<gbNW, TB>>>(b3, out, N);
}

// round 7
// speedup vs baseline: 1.7328x; 1.0580x over previous
#include <cuda_runtime.h>
#include <cstdint>

#define NMAX 50000
#define EMAX 800000
#define FDIM 128
#define CDIM 40
#define SCAN_T 1024
#define STATS_B 512

// ---------------- device scratch (static allocation; no cudaMalloc) ----------
__device__ float g_xw [NMAX * FDIM];   // GEMM output of current layer
__device__ float g_h  [NMAX * FDIM];   // aggregated hidden state (pre-BN)
__device__ float g_xw3[NMAX * CDIM];   // layer-3 GEMM output
__device__ float g_deg [NMAX];         // edge-weight in-degree (without self loop)
__device__ float g_dinv[NMAX];
__device__ int   g_cnt   [NMAX];       // in-degree counts
__device__ int   g_rowptr[NMAX + 1];   // CSR row pointers (by dst)
__device__ int   g_cursor[NMAX];       // fill cursors
__device__ int2  g_csr   [EMAX];       // packed {src, bitcast(norm)}
__device__ float g_psum  [STATS_B][FDIM];   // BN partial sums
__device__ float g_psumsq[STATS_B][FDIM];
__device__ float g_scale[FDIM];
__device__ float g_shift[FDIM];

// ---------------- graph preprocessing ----------------------------------------
// edge_index is int32 (JAX x64 disabled downcasts jnp.int64 -> int32).
__global__ void k_zero(int N) {
    int i = blockIdx.x * blockDim.x + threadIdx.x;
    if (i < N) { g_deg[i] = 0.f; g_cnt[i] = 0; }
}

__global__ void k_deg_cnt(const int* __restrict__ ei,
                          const float* __restrict__ ew, int E, int N) {
    int e = blockIdx.x * blockDim.x + threadIdx.x;
    if (e >= E) return;
    int d = ei[E + e];
    if ((unsigned)d < (unsigned)N) {
        atomicAdd(&g_deg[d], ew[e]);
        atomicAdd(&g_cnt[d], 1);
    }
}

// dinv prologue + single-block exclusive scan over counts -> rowptr + cursor
__global__ void k_scan_dinv(int N) {
    __shared__ int sh[SCAN_T];
    int tid = threadIdx.x;
    for (int i = tid; i < N; i += SCAN_T)
        g_dinv[i] = rsqrtf(g_deg[i] + 1.0f);   // +1 = self-loop weight
    __syncthreads();
    int chunk = (N + SCAN_T - 1) / SCAN_T;
    int start = tid * chunk;
    int end   = min(start + chunk, N);
    int sum = 0;
    for (int i = start; i < end; i++) sum += g_cnt[i];
    sh[tid] = sum;
    __syncthreads();
    for (int off = 1; off < SCAN_T; off <<= 1) {
        int v = (tid >= off) ? sh[tid - off] : 0;
        __syncthreads();
        sh[tid] += v;
        __syncthreads();
    }
    int off = sh[tid] - sum;   // exclusive prefix
    for (int i = start; i < end; i++) {
        g_rowptr[i] = off;
        g_cursor[i] = off;
        off += g_cnt[i];
    }
    if (tid == SCAN_T - 1) g_rowptr[N] = off;
}

// norm compute + CSR fill in one pass (src/dst/norm arrays eliminated)
__global__ void k_csr_build(const int* __restrict__ ei,
                            const float* __restrict__ ew, int E, int N) {
    int e = blockIdx.x * blockDim.x + threadIdx.x;
    if (e >= E) return;
    int s = ei[e];
    int d = ei[E + e];
    if ((unsigned)s >= (unsigned)N) s = 0;
    if ((unsigned)d >= (unsigned)N) d = 0;
    float nrm = g_dinv[s] * ew[e] * g_dinv[d];
    int pos = atomicAdd(&g_cursor[d], 1);
    g_csr[pos] = make_int2(s, __float_as_int(nrm));
}

// ---------------- SGEMM: [M,128] @ [128,128] ---------------------------------
// bnsel: 0 -> A = external x (plain). 1 -> A = relu(g_h*scale + shift) applied
// on the fly per feature column during the smem stage. Output g_xw.
__global__ __launch_bounds__(256) void k_gemm128(const float* __restrict__ Aext,
                                                 int bnsel,
                                                 const float* __restrict__ B,
                                                 int M) {
    const float* __restrict__ A = bnsel ? (const float*)g_h : Aext;
    __shared__ float As[16][128];   // transposed: [k][row]
    __shared__ float Bs[16][128];   // [k][col]
    const int tid  = threadIdx.x;
    const int tx   = tid & 15;
    const int ty   = tid >> 4;
    const int row0 = blockIdx.x * 128;
    const int a_row = tid >> 1;
    const int a_k4  = (tid & 1) * 8;
    const int b_k   = tid >> 4;
    const int b_n   = (tid & 15) * 8;

    float acc[8][8];
#pragma unroll
    for (int i = 0; i < 8; i++)
#pragma unroll
        for (int j = 0; j < 8; j++) acc[i][j] = 0.f;

#pragma unroll 1
    for (int k0 = 0; k0 < 128; k0 += 16) {
        int grow = row0 + a_row;
        float4 av0 = make_float4(0.f, 0.f, 0.f, 0.f);
        float4 av1 = av0;
        if (grow < M) {
            const float* ap = A + (size_t)grow * 128 + k0 + a_k4;
            av0 = *(const float4*)ap;
            av1 = *(const float4*)(ap + 4);
            if (bnsel) {   // fused BN apply + ReLU (column-wise)
                int c4 = (k0 + a_k4) >> 2;
                float4 sc0 = ((const float4*)g_scale)[c4];
                float4 sc1 = ((const float4*)g_scale)[c4 + 1];
                float4 sh0 = ((const float4*)g_shift)[c4];
                float4 sh1 = ((const float4*)g_shift)[c4 + 1];
                av0.x = fmaxf(0.f, fmaf(av0.x, sc0.x, sh0.x));
                av0.y = fmaxf(0.f, fmaf(av0.y, sc0.y, sh0.y));
                av0.z = fmaxf(0.f, fmaf(av0.z, sc0.z, sh0.z));
                av0.w = fmaxf(0.f, fmaf(av0.w, sc0.w, sh0.w));
                av1.x = fmaxf(0.f, fmaf(av1.x, sc1.x, sh1.x));
                av1.y = fmaxf(0.f, fmaf(av1.y, sc1.y, sh1.y));
                av1.z = fmaxf(0.f, fmaf(av1.z, sc1.z, sh1.z));
                av1.w = fmaxf(0.f, fmaf(av1.w, sc1.w, sh1.w));
            }
        }
        As[a_k4 + 0][a_row] = av0.x; As[a_k4 + 1][a_row] = av0.y;
        As[a_k4 + 2][a_row] = av0.z; As[a_k4 + 3][a_row] = av0.w;
        As[a_k4 + 4][a_row] = av1.x; As[a_k4 + 5][a_row] = av1.y;
        As[a_k4 + 6][a_row] = av1.z; As[a_k4 + 7][a_row] = av1.w;

        const float* bp = B + (size_t)(k0 + b_k) * 128 + b_n;
        *(float4*)&Bs[b_k][b_n]     = *(const float4*)bp;
        *(float4*)&Bs[b_k][b_n + 4] = *(const float4*)(bp + 4);
        __syncthreads();

#pragma unroll
        for (int kk = 0; kk < 16; kk++) {
            float ar[8], br[8];
            *(float4*)&ar[0] = *(const float4*)&As[kk][ty * 8];
            *(float4*)&ar[4] = *(const float4*)&As[kk][ty * 8 + 4];
            *(float4*)&br[0] = *(const float4*)&Bs[kk][tx * 8];
            *(float4*)&br[4] = *(const float4*)&Bs[kk][tx * 8 + 4];
#pragma unroll
            for (int i = 0; i < 8; i++)
#pragma unroll
                for (int j = 0; j < 8; j++)
                    acc[i][j] = fmaf(ar[i], br[j], acc[i][j]);
        }
        __syncthreads();
    }

#pragma unroll
    for (int i = 0; i < 8; i++) {
        int r = row0 + ty * 8 + i;
        if (r < M) {
            float4 o0 = make_float4(acc[i][0], acc[i][1], acc[i][2], acc[i][3]);
            float4 o1 = make_float4(acc[i][4], acc[i][5], acc[i][6], acc[i][7]);
            *(float4*)(g_xw + (size_t)r * 128 + tx * 8)     = o0;
            *(float4*)(g_xw + (size_t)r * 128 + tx * 8 + 4) = o1;
        }
    }
}

// ---------------- SGEMM: [M,128] @ [128,40]  (BN2+relu(g_h) -> g_xw3) ---------
__global__ __launch_bounds__(256) void k_gemm40(const float* __restrict__ B,
                                                int M) {
    __shared__ float As[16][128];
    __shared__ float Bs[16][40];
    const int tid  = threadIdx.x;
    const int tx   = tid & 7;
    const int ty   = tid >> 3;
    const int row0 = blockIdx.x * 128;
    const int a_row = tid >> 1;
    const int a_k4  = (tid & 1) * 8;

    float acc[4][5];
#pragma unroll
    for (int i = 0; i < 4; i++)
#pragma unroll
        for (int j = 0; j < 5; j++) acc[i][j] = 0.f;

#pragma unroll 1
    for (int k0 = 0; k0 < 128; k0 += 16) {
        int grow = row0 + a_row;
        float4 av0 = make_float4(0.f, 0.f, 0.f, 0.f);
        float4 av1 = av0;
        if (grow < M) {
            const float* ap = g_h + (size_t)grow * 128 + k0 + a_k4;
            av0 = *(const float4*)ap;
            av1 = *(const float4*)(ap + 4);
            int c4 = (k0 + a_k4) >> 2;
            float4 sc0 = ((const float4*)g_scale)[c4];
            float4 sc1 = ((const float4*)g_scale)[c4 + 1];
            float4 sh0 = ((const float4*)g_shift)[c4];
            float4 sh1 = ((const float4*)g_shift)[c4 + 1];
            av0.x = fmaxf(0.f, fmaf(av0.x, sc0.x, sh0.x));
            av0.y = fmaxf(0.f, fmaf(av0.y, sc0.y, sh0.y));
            av0.z = fmaxf(0.f, fmaf(av0.z, sc0.z, sh0.z));
            av0.w = fmaxf(0.f, fmaf(av0.w, sc0.w, sh0.w));
            av1.x = fmaxf(0.f, fmaf(av1.x, sc1.x, sh1.x));
            av1.y = fmaxf(0.f, fmaf(av1.y, sc1.y, sh1.y));
            av1.z = fmaxf(0.f, fmaf(av1.z, sc1.z, sh1.z));
            av1.w = fmaxf(0.f, fmaf(av1.w, sc1.w, sh1.w));
        }
        As[a_k4 + 0][a_row] = av0.x; As[a_k4 + 1][a_row] = av0.y;
        As[a_k4 + 2][a_row] = av0.z; As[a_k4 + 3][a_row] = av0.w;
        As[a_k4 + 4][a_row] = av1.x; As[a_k4 + 5][a_row] = av1.y;
        As[a_k4 + 6][a_row] = av1.z; As[a_k4 + 7][a_row] = av1.w;

        for (int i = tid; i < 16 * 40; i += 256) {
            int bk = i / 40, bn = i % 40;
            Bs[bk][bn] = B[(size_t)(k0 + bk) * 40 + bn];
        }
        __syncthreads();

#pragma unroll
        for (int kk = 0; kk < 16; kk++) {
            float ar[4], br[5];
#pragma unroll
            for (int i = 0; i < 4; i++) ar[i] = As[kk][ty * 4 + i];
#pragma unroll
            for (int j = 0; j < 5; j++) br[j] = Bs[kk][tx * 5 + j];
#pragma unroll
            for (int i = 0; i < 4; i++)
#pragma unroll
                for (int j = 0; j < 5; j++)
                    acc[i][j] = fmaf(ar[i], br[j], acc[i][j]);
        }
        __syncthreads();
    }

#pragma unroll
    for (int i = 0; i < 4; i++) {
        int r = row0 + ty * 4 + i;
        if (r < M) {
#pragma unroll
            for (int j = 0; j < 5; j++)
                g_xw3[(size_t)r * 40 + tx * 5 + j] = acc[i][j];
        }
    }
}

// ---------------- CSR gather aggregation --------------------------------------
// one block (128 threads) per node:
// g_h[n][c] = b[c] + dinv[n]^2 * g_xw[n][c] + sum_j norm_j * g_xw[src_j][c]
__global__ __launch_bounds__(128) void k_gather128(const float* __restrict__ b,
                                                   int N) {
    int n = blockIdx.x;
    int c = threadIdx.x;
    float di = g_dinv[n]; di *= di;
    float acc0 = fmaf(di, g_xw[(size_t)n * 128 + c], b[c]);
    float acc1 = 0.f, acc2 = 0.f, acc3 = 0.f;
    int j   = g_rowptr[n];
    int end = g_rowptr[n + 1];
    for (; j + 3 < end; j += 4) {          // MLP=4 against L2 latency
        int2 e0 = g_csr[j],     e1 = g_csr[j + 1];
        int2 e2 = g_csr[j + 2], e3 = g_csr[j + 3];
        acc0 = fmaf(__int_as_float(e0.y), g_xw[(size_t)e0.x * 128 + c], acc0);
        acc1 = fmaf(__int_as_float(e1.y), g_xw[(size_t)e1.x * 128 + c], acc1);
        acc2 = fmaf(__int_as_float(e2.y), g_xw[(size_t)e2.x * 128 + c], acc2);
        acc3 = fmaf(__int_as_float(e3.y), g_xw[(size_t)e3.x * 128 + c], acc3);
    }
    for (; j < end; j++) {
        int2 e = g_csr[j];
        acc0 = fmaf(__int_as_float(e.y), g_xw[(size_t)e.x * 128 + c], acc0);
    }
    g_h[(size_t)n * 128 + c] = (acc0 + acc1) + (acc2 + acc3);
}

// layer 3: gather + bias + self-loop + log_softmax, one warp per node
__global__ void k_gather40_lsm(const float* __restrict__ b3,
                               float* __restrict__ out, int N) {
    int t = blockIdx.x * blockDim.x + threadIdx.x;
    int n = t >> 5, lane = t & 31;
    if (n >= N) return;
    float di = g_dinv[n]; di *= di;
    const float* xr = g_xw3 + (size_t)n * 40;
    float v1 = fmaf(di, xr[lane], b3[lane]);
    float v2 = (lane < 8) ? fmaf(di, xr[32 + lane], b3[32 + lane]) : 0.f;
    int j   = g_rowptr[n];
    int end = g_rowptr[n + 1];
    for (; j < end; j++) {
        int2 e = g_csr[j];
        float w = __int_as_float(e.y);
        const float* sr = g_xw3 + (size_t)e.x * 40;
        v1 = fmaf(w, sr[lane], v1);
        if (lane < 8) v2 = fmaf(w, sr[32 + lane], v2);
    }
    float m = (lane < 8) ? fmaxf(v1, v2) : v1;
#pragma unroll
    for (int o = 16; o > 0; o >>= 1) m = fmaxf(m, __shfl_xor_sync(0xffffffffu, m, o));
    float s = expf(v1 - m) + ((lane < 8) ? expf(v2 - m) : 0.f);
#pragma unroll
    for (int o = 16; o > 0; o >>= 1) s += __shfl_xor_sync(0xffffffffu, s, o);
    float l = m + logf(s);
    float* p = out + (size_t)n * 40;
    p[lane] = v1 - l;
    if (lane < 8) p[32 + lane] = v2 - l;
}

// ---------------- batch norm (deterministic partials) -------------------------
__global__ void k_bn_stats(int N) {
    int col = threadIdx.x;            // 128 threads, STATS_B blocks
    float s = 0.f, s2 = 0.f;
    for (int r = blockIdx.x; r < N; r += STATS_B) {
        float v = g_h[(size_t)r * 128 + col];
        s += v; s2 += v * v;
    }
    g_psum  [blockIdx.x][col] = s;
    g_psumsq[blockIdx.x][col] = s2;
}

// 1024 threads: 8 groups x 128 cols, each group sums 64 partials, smem combine
__global__ void k_bn_reduce(const float* __restrict__ gamma,
                            const float* __restrict__ beta, float invN) {
    __shared__ float sh1[8][FDIM];
    __shared__ float sh2[8][FDIM];
    int col = threadIdx.x & 127;
    int grp = threadIdx.x >> 7;       // 0..7
    float s = 0.f, s2 = 0.f;
    for (int b = grp * (STATS_B / 8); b < (grp + 1) * (STATS_B / 8); b++) {
        s  += g_psum  [b][col];
        s2 += g_psumsq[b][col];
    }
    sh1[grp][col] = s;
    sh2[grp][col] = s2;
    __syncthreads();
    if (grp == 0) {
        float ts = 0.f, ts2 = 0.f;
#pragma unroll
        for (int g = 0; g < 8; g++) { ts += sh1[g][col]; ts2 += sh2[g][col]; }
        float mean = ts * invN;
        float var  = fmaf(-mean, mean, ts2 * invN);
        float sc   = gamma[col] * rsqrtf(var + 1e-5f);
        g_scale[col] = sc;
        g_shift[col] = fmaf(-mean, sc, beta[col]);
    }
}

// ---------------- launch -----------------------------------------------------
extern "C" void kernel_launch(void* const* d_in, const int* in_sizes, int n_in,
                              void* d_out, int out_size) {
    const float* x   = (const float*)d_in[0];
    const int*   ei  = (const int*)d_in[1];     // int32 (JAX x64 disabled)
    const float* ew  = (const float*)d_in[2];
    const float* W1  = (const float*)d_in[3];
    const float* b1  = (const float*)d_in[4];
    const float* ga1 = (const float*)d_in[5];
    const float* be1 = (const float*)d_in[6];
    const float* W2  = (const float*)d_in[7];
    const float* b2  = (const float*)d_in[8];
    const float* ga2 = (const float*)d_in[9];
    const float* be2 = (const float*)d_in[10];
    const float* W3  = (const float*)d_in[11];
    const float* b3  = (const float*)d_in[12];
    float* out = (float*)d_out;

    int N = in_sizes[0] / FDIM;
    int E = in_sizes[2];

    const int TB = 256;
    int gbN  = (N + TB - 1) / TB;
    int gbE  = (E + TB - 1) / TB;
    int gbM  = (N + 127) / 128;
    int gbNW = (N * 32 + TB - 1) / TB;      // warp-per-node

    // ---- graph preprocessing + CSR build (4 kernels) ----
    k_zero     <<<gbN, TB>>>(N);
    k_deg_cnt  <<<gbE, TB>>>(ei, ew, E, N);
    k_scan_dinv<<<1, SCAN_T>>>(N);
    k_csr_build<<<gbE, TB>>>(ei, ew, E, N);

    // ---- layer 1 ----
    k_gemm128  <<<gbM, 256>>>(x, 0, W1, N);
    k_gather128<<<N, 128>>>(b1, N);
    k_bn_stats <<<STATS_B, 128>>>(N);
    k_bn_reduce<<<1, 1024>>>(ga1, be1, 1.0f / (float)N);

    // ---- layer 2 (BN1+relu fused into gemm A-load) ----
    k_gemm128  <<<gbM, 256>>>(x, 1, W2, N);
    k_gather128<<<N, 128>>>(b2, N);
    k_bn_stats <<<STATS_B, 128>>>(N);
    k_bn_reduce<<<1, 1024>>>(ga2, be2, 1.0f / (float)N);

    // ---- layer 3 (BN2+relu fused) + log_softmax ----
    k_gemm40       <<<gbM, 256>>>(W3, N);
    k_gather40_lsm <<<gbNW, TB>>>(b3, out, N);
}

// round 8
// speedup vs baseline: 1.9813x; 1.1434x over previous
#include <cuda_runtime.h>
#include <cstdint>

#define NMAX 50000
#define EMAX 800000
#define FDIM 128
#define CDIM 40
#define SCAN_T 1024
#define STATS_B 512

// ---------------- device scratch (static allocation; no cudaMalloc) ----------
__device__ float g_xw [NMAX * FDIM];   // GEMM output of current layer
__device__ float g_h  [NMAX * FDIM];   // aggregated hidden state (pre-BN)
__device__ float g_xw3[NMAX * CDIM];   // layer-3 GEMM output
__device__ float g_deg [NMAX];         // edge-weight in-degree (without self loop)
__device__ float g_dinv[NMAX];
__device__ int   g_cnt   [NMAX];       // in-degree counts
__device__ int   g_rowptr[NMAX + 1];   // CSR row pointers (by dst)
__device__ int   g_cursor[NMAX];       // fill cursors
__device__ int2  g_csr   [EMAX];       // packed {src, bitcast(norm)}
__device__ float g_psum  [STATS_B][FDIM];   // BN partial sums   (zero-invariant:
__device__ float g_psumsq[STATS_B][FDIM];   //  bn_reduce re-zeroes after reading)
__device__ float g_scale[FDIM];
__device__ float g_shift[FDIM];

// ---------------- graph preprocessing ----------------------------------------
// edge_index is int32 (JAX x64 disabled downcasts jnp.int64 -> int32).
__global__ void k_zero(int N) {
    int i = blockIdx.x * blockDim.x + threadIdx.x;
    if (i < N) { g_deg[i] = 0.f; g_cnt[i] = 0; }
}

__global__ void k_deg_cnt(const int* __restrict__ ei,
                          const float* __restrict__ ew, int E, int N) {
    int e = blockIdx.x * blockDim.x + threadIdx.x;
    if (e >= E) return;
    int d = ei[E + e];
    if ((unsigned)d < (unsigned)N) {
        atomicAdd(&g_deg[d], ew[e]);
        atomicAdd(&g_cnt[d], 1);
    }
}

// dinv prologue + single-block exclusive scan over counts -> rowptr + cursor
__global__ void k_scan_dinv(int N) {
    __shared__ int sh[SCAN_T];
    int tid = threadIdx.x;
    for (int i = tid; i < N; i += SCAN_T)
        g_dinv[i] = rsqrtf(g_deg[i] + 1.0f);   // +1 = self-loop weight
    __syncthreads();
    int chunk = (N + SCAN_T - 1) / SCAN_T;
    int start = tid * chunk;
    int end   = min(start + chunk, N);
    int sum = 0;
    for (int i = start; i < end; i++) sum += g_cnt[i];
    sh[tid] = sum;
    __syncthreads();
    for (int off = 1; off < SCAN_T; off <<= 1) {
        int v = (tid >= off) ? sh[tid - off] : 0;
        __syncthreads();
        sh[tid] += v;
        __syncthreads();
    }
    int off = sh[tid] - sum;   // exclusive prefix
    for (int i = start; i < end; i++) {
        g_rowptr[i] = off;
        g_cursor[i] = off;
        off += g_cnt[i];
    }
    if (tid == SCAN_T - 1) g_rowptr[N] = off;
}

// norm compute + CSR fill in one pass
__global__ void k_csr_build(const int* __restrict__ ei,
                            const float* __restrict__ ew, int E, int N) {
    int e = blockIdx.x * blockDim.x + threadIdx.x;
    if (e >= E) return;
    int s = ei[e];
    int d = ei[E + e];
    if ((unsigned)s >= (unsigned)N) s = 0;
    if ((unsigned)d >= (unsigned)N) d = 0;
    float nrm = g_dinv[s] * ew[e] * g_dinv[d];
    int pos = atomicAdd(&g_cursor[d], 1);
    g_csr[pos] = make_int2(s, __float_as_int(nrm));
}

// ---------------- SGEMM: [M,128] @ [128,128] ---------------------------------
// bnsel: 0 -> A = external x (plain). 1 -> A = relu(g_h*scale + shift) applied
// on the fly per feature column during the smem stage. Output g_xw.
__global__ __launch_bounds__(256) void k_gemm128(const float* __restrict__ Aext,
                                                 int bnsel,
                                                 const float* __restrict__ B,
                                                 int M) {
    const float* __restrict__ A = bnsel ? (const float*)g_h : Aext;
    __shared__ float As[16][128];   // transposed: [k][row]
    __shared__ float Bs[16][128];   // [k][col]
    const int tid  = threadIdx.x;
    const int tx   = tid & 15;
    const int ty   = tid >> 4;
    const int row0 = blockIdx.x * 128;
    const int a_row = tid >> 1;
    const int a_k4  = (tid & 1) * 8;
    const int b_k   = tid >> 4;
    const int b_n   = (tid & 15) * 8;

    float acc[8][8];
#pragma unroll
    for (int i = 0; i < 8; i++)
#pragma unroll
        for (int j = 0; j < 8; j++) acc[i][j] = 0.f;

#pragma unroll 1
    for (int k0 = 0; k0 < 128; k0 += 16) {
        int grow = row0 + a_row;
        float4 av0 = make_float4(0.f, 0.f, 0.f, 0.f);
        float4 av1 = av0;
        if (grow < M) {
            const float* ap = A + (size_t)grow * 128 + k0 + a_k4;
            av0 = *(const float4*)ap;
            av1 = *(const float4*)(ap + 4);
            if (bnsel) {   // fused BN apply + ReLU (column-wise)
                int c4 = (k0 + a_k4) >> 2;
                float4 sc0 = ((const float4*)g_scale)[c4];
                float4 sc1 = ((const float4*)g_scale)[c4 + 1];
                float4 sh0 = ((const float4*)g_shift)[c4];
                float4 sh1 = ((const float4*)g_shift)[c4 + 1];
                av0.x = fmaxf(0.f, fmaf(av0.x, sc0.x, sh0.x));
                av0.y = fmaxf(0.f, fmaf(av0.y, sc0.y, sh0.y));
                av0.z = fmaxf(0.f, fmaf(av0.z, sc0.z, sh0.z));
                av0.w = fmaxf(0.f, fmaf(av0.w, sc0.w, sh0.w));
                av1.x = fmaxf(0.f, fmaf(av1.x, sc1.x, sh1.x));
                av1.y = fmaxf(0.f, fmaf(av1.y, sc1.y, sh1.y));
                av1.z = fmaxf(0.f, fmaf(av1.z, sc1.z, sh1.z));
                av1.w = fmaxf(0.f, fmaf(av1.w, sc1.w, sh1.w));
            }
        }
        As[a_k4 + 0][a_row] = av0.x; As[a_k4 + 1][a_row] = av0.y;
        As[a_k4 + 2][a_row] = av0.z; As[a_k4 + 3][a_row] = av0.w;
        As[a_k4 + 4][a_row] = av1.x; As[a_k4 + 5][a_row] = av1.y;
        As[a_k4 + 6][a_row] = av1.z; As[a_k4 + 7][a_row] = av1.w;

        const float* bp = B + (size_t)(k0 + b_k) * 128 + b_n;
        *(float4*)&Bs[b_k][b_n]     = *(const float4*)bp;
        *(float4*)&Bs[b_k][b_n + 4] = *(const float4*)(bp + 4);
        __syncthreads();

#pragma unroll
        for (int kk = 0; kk < 16; kk++) {
            float ar[8], br[8];
            *(float4*)&ar[0] = *(const float4*)&As[kk][ty * 8];
            *(float4*)&ar[4] = *(const float4*)&As[kk][ty * 8 + 4];
            *(float4*)&br[0] = *(const float4*)&Bs[kk][tx * 8];
            *(float4*)&br[4] = *(const float4*)&Bs[kk][tx * 8 + 4];
#pragma unroll
            for (int i = 0; i < 8; i++)
#pragma unroll
                for (int j = 0; j < 8; j++)
                    acc[i][j] = fmaf(ar[i], br[j], acc[i][j]);
        }
        __syncthreads();
    }

#pragma unroll
    for (int i = 0; i < 8; i++) {
        int r = row0 + ty * 8 + i;
        if (r < M) {
            float4 o0 = make_float4(acc[i][0], acc[i][1], acc[i][2], acc[i][3]);
            float4 o1 = make_float4(acc[i][4], acc[i][5], acc[i][6], acc[i][7]);
            *(float4*)(g_xw + (size_t)r * 128 + tx * 8)     = o0;
            *(float4*)(g_xw + (size_t)r * 128 + tx * 8 + 4) = o1;
        }
    }
}

// ---------------- SGEMM: [M,128] @ [128,40]  (BN2+relu(g_h) -> g_xw3) ---------
__global__ __launch_bounds__(256) void k_gemm40(const float* __restrict__ B,
                                                int M) {
    __shared__ float As[16][128];
    __shared__ float Bs[16][40];
    const int tid  = threadIdx.x;
    const int tx   = tid & 7;
    const int ty   = tid >> 3;
    const int row0 = blockIdx.x * 128;
    const int a_row = tid >> 1;
    const int a_k4  = (tid & 1) * 8;

    float acc[4][5];
#pragma unroll
    for (int i = 0; i < 4; i++)
#pragma unroll
        for (int j = 0; j < 5; j++) acc[i][j] = 0.f;

#pragma unroll 1
    for (int k0 = 0; k0 < 128; k0 += 16) {
        int grow = row0 + a_row;
        float4 av0 = make_float4(0.f, 0.f, 0.f, 0.f);
        float4 av1 = av0;
        if (grow < M) {
            const float* ap = g_h + (size_t)grow * 128 + k0 + a_k4;
            av0 = *(const float4*)ap;
            av1 = *(const float4*)(ap + 4);
            int c4 = (k0 + a_k4) >> 2;
            float4 sc0 = ((const float4*)g_scale)[c4];
            float4 sc1 = ((const float4*)g_scale)[c4 + 1];
            float4 sh0 = ((const float4*)g_shift)[c4];
            float4 sh1 = ((const float4*)g_shift)[c4 + 1];
            av0.x = fmaxf(0.f, fmaf(av0.x, sc0.x, sh0.x));
            av0.y = fmaxf(0.f, fmaf(av0.y, sc0.y, sh0.y));
            av0.z = fmaxf(0.f, fmaf(av0.z, sc0.z, sh0.z));
            av0.w = fmaxf(0.f, fmaf(av0.w, sc0.w, sh0.w));
            av1.x = fmaxf(0.f, fmaf(av1.x, sc1.x, sh1.x));
            av1.y = fmaxf(0.f, fmaf(av1.y, sc1.y, sh1.y));
            av1.z = fmaxf(0.f, fmaf(av1.z, sc1.z, sh1.z));
            av1.w = fmaxf(0.f, fmaf(av1.w, sc1.w, sh1.w));
        }
        As[a_k4 + 0][a_row] = av0.x; As[a_k4 + 1][a_row] = av0.y;
        As[a_k4 + 2][a_row] = av0.z; As[a_k4 + 3][a_row] = av0.w;
        As[a_k4 + 4][a_row] = av1.x; As[a_k4 + 5][a_row] = av1.y;
        As[a_k4 + 6][a_row] = av1.z; As[a_k4 + 7][a_row] = av1.w;

        for (int i = tid; i < 16 * 40; i += 256) {
            int bk = i / 40, bn = i % 40;
            Bs[bk][bn] = B[(size_t)(k0 + bk) * 40 + bn];
        }
        __syncthreads();

#pragma unroll
        for (int kk = 0; kk < 16; kk++) {
            float ar[4], br[5];
#pragma unroll
            for (int i = 0; i < 4; i++) ar[i] = As[kk][ty * 4 + i];
#pragma unroll
            for (int j = 0; j < 5; j++) br[j] = Bs[kk][tx * 5 + j];
#pragma unroll
            for (int i = 0; i < 4; i++)
#pragma unroll
                for (int j = 0; j < 5; j++)
                    acc[i][j] = fmaf(ar[i], br[j], acc[i][j]);
        }
        __syncthreads();
    }

#pragma unroll
    for (int i = 0; i < 4; i++) {
        int r = row0 + ty * 4 + i;
        if (r < M) {
#pragma unroll
            for (int j = 0; j < 5; j++)
                g_xw3[(size_t)r * 40 + tx * 5 + j] = acc[i][j];
        }
    }
}

// ---------------- CSR gather + fused BN partial stats -------------------------
// 256 threads = 8 warps; warp w handles node n = blockIdx*8 + w.
// Lane t owns columns 4t..4t+3 (one float4 / LDG.128 per edge).
// Epilogue: 8-node smem reduce of (h, h^2), warp 0 atomically folds into
// g_psum/g_psumsq[blockIdx % STATS_B].
__global__ __launch_bounds__(256) void k_gather128(const float* __restrict__ b,
                                                   int N) {
    __shared__ float4 sh_s [8][32];
    __shared__ float4 sh_s2[8][32];
    const int warp = threadIdx.x >> 5;
    const int lane = threadIdx.x & 31;
    const int n = blockIdx.x * 8 + warp;

    float4 a0 = make_float4(0.f, 0.f, 0.f, 0.f);
    float4 a1 = a0, a2 = a0, a3 = a0;

    if (n < N) {
        float di = g_dinv[n]; di *= di;
        float4 bv = ((const float4*)b)[lane];
        float4 xv = ((const float4*)g_xw)[(size_t)n * 32 + lane];
        a0.x = fmaf(di, xv.x, bv.x); a0.y = fmaf(di, xv.y, bv.y);
        a0.z = fmaf(di, xv.z, bv.z); a0.w = fmaf(di, xv.w, bv.w);

        int j   = g_rowptr[n];
        int end = g_rowptr[n + 1];
        for (; j + 3 < end; j += 4) {          // 4 edge-parallel float4 streams
            int2 e0 = g_csr[j],     e1 = g_csr[j + 1];
            int2 e2 = g_csr[j + 2], e3 = g_csr[j + 3];
            float4 v0 = ((const float4*)g_xw)[(size_t)e0.x * 32 + lane];
            float4 v1 = ((const float4*)g_xw)[(size_t)e1.x * 32 + lane];
            float4 v2 = ((const float4*)g_xw)[(size_t)e2.x * 32 + lane];
            float4 v3 = ((const float4*)g_xw)[(size_t)e3.x * 32 + lane];
            float w0 = __int_as_float(e0.y), w1 = __int_as_float(e1.y);
            float w2 = __int_as_float(e2.y), w3 = __int_as_float(e3.y);
            a0.x = fmaf(w0, v0.x, a0.x); a0.y = fmaf(w0, v0.y, a0.y);
            a0.z = fmaf(w0, v0.z, a0.z); a0.w = fmaf(w0, v0.w, a0.w);
            a1.x = fmaf(w1, v1.x, a1.x); a1.y = fmaf(w1, v1.y, a1.y);
            a1.z = fmaf(w1, v1.z, a1.z); a1.w = fmaf(w1, v1.w, a1.w);
            a2.x = fmaf(w2, v2.x, a2.x); a2.y = fmaf(w2, v2.y, a2.y);
            a2.z = fmaf(w2, v2.z, a2.z); a2.w = fmaf(w2, v2.w, a2.w);
            a3.x = fmaf(w3, v3.x, a3.x); a3.y = fmaf(w3, v3.y, a3.y);
            a3.z = fmaf(w3, v3.z, a3.z); a3.w = fmaf(w3, v3.w, a3.w);
        }
        for (; j < end; j++) {
            int2 e = g_csr[j];
            float4 v = ((const float4*)g_xw)[(size_t)e.x * 32 + lane];
            float w = __int_as_float(e.y);
            a0.x = fmaf(w, v.x, a0.x); a0.y = fmaf(w, v.y, a0.y);
            a0.z = fmaf(w, v.z, a0.z); a0.w = fmaf(w, v.w, a0.w);
        }
        a0.x = (a0.x + a1.x) + (a2.x + a3.x);
        a0.y = (a0.y + a1.y) + (a2.y + a3.y);
        a0.z = (a0.z + a1.z) + (a2.z + a3.z);
        a0.w = (a0.w + a1.w) + (a2.w + a3.w);
        ((float4*)g_h)[(size_t)n * 32 + lane] = a0;
    } else {
        a0 = make_float4(0.f, 0.f, 0.f, 0.f);
    }

    // BN partial-stat epilogue
    sh_s [warp][lane] = a0;
    sh_s2[warp][lane] = make_float4(a0.x * a0.x, a0.y * a0.y,
                                    a0.z * a0.z, a0.w * a0.w);
    __syncthreads();
    if (warp == 0) {
        float4 ts  = make_float4(0.f, 0.f, 0.f, 0.f);
        float4 ts2 = ts;
#pragma unroll
        for (int g = 0; g < 8; g++) {
            float4 s  = sh_s [g][lane];
            float4 s2 = sh_s2[g][lane];
            ts.x += s.x;  ts.y += s.y;  ts.z += s.z;  ts.w += s.w;
            ts2.x += s2.x; ts2.y += s2.y; ts2.z += s2.z; ts2.w += s2.w;
        }
        int slot = blockIdx.x & (STATS_B - 1);
        float* ps  = &g_psum  [slot][lane * 4];
        float* ps2 = &g_psumsq[slot][lane * 4];
        atomicAdd(ps + 0, ts.x);  atomicAdd(ps + 1, ts.y);
        atomicAdd(ps + 2, ts.z);  atomicAdd(ps + 3, ts.w);
        atomicAdd(ps2 + 0, ts2.x); atomicAdd(ps2 + 1, ts2.y);
        atomicAdd(ps2 + 2, ts2.z); atomicAdd(ps2 + 3, ts2.w);
    }
}

// layer 3: gather + bias + self-loop + log_softmax, one warp per node
__global__ void k_gather40_lsm(const float* __restrict__ b3,
                               float* __restrict__ out, int N) {
    int t = blockIdx.x * blockDim.x + threadIdx.x;
    int n = t >> 5, lane = t & 31;
    if (n >= N) return;
    float di = g_dinv[n]; di *= di;
    const float* xr = g_xw3 + (size_t)n * 40;
    float v1 = fmaf(di, xr[lane], b3[lane]);
    float v2 = (lane < 8) ? fmaf(di, xr[32 + lane], b3[32 + lane]) : 0.f;
    int j   = g_rowptr[n];
    int end = g_rowptr[n + 1];
    for (; j < end; j++) {
        int2 e = g_csr[j];
        float w = __int_as_float(e.y);
        const float* sr = g_xw3 + (size_t)e.x * 40;
        v1 = fmaf(w, sr[lane], v1);
        if (lane < 8) v2 = fmaf(w, sr[32 + lane], v2);
    }
    float m = (lane < 8) ? fmaxf(v1, v2) : v1;
#pragma unroll
    for (int o = 16; o > 0; o >>= 1) m = fmaxf(m, __shfl_xor_sync(0xffffffffu, m, o));
    float s = expf(v1 - m) + ((lane < 8) ? expf(v2 - m) : 0.f);
#pragma unroll
    for (int o = 16; o > 0; o >>= 1) s += __shfl_xor_sync(0xffffffffu, s, o);
    float l = m + logf(s);
    float* p = out + (size_t)n * 40;
    p[lane] = v1 - l;
    if (lane < 8) p[32 + lane] = v2 - l;
}

// ---------------- batch norm reduce (also re-zeroes partials) -----------------
// 1024 threads: 8 groups x 128 cols, each group sums 64 partials, smem combine.
// After reading, partial slots are zeroed so the next layer / next graph replay
// starts from a clean state (device globals are zero-initialized at load).
__global__ void k_bn_reduce(const float* __restrict__ gamma,
                            const float* __restrict__ beta, float invN) {
    __shared__ float sh1[8][FDIM];
    __shared__ float sh2[8][FDIM];
    int col = threadIdx.x & 127;
    int grp = threadIdx.x >> 7;       // 0..7
    float s = 0.f, s2 = 0.f;
    for (int b = grp * (STATS_B / 8); b < (grp + 1) * (STATS_B / 8); b++) {
        s  += g_psum  [b][col];
        s2 += g_psumsq[b][col];
        g_psum  [b][col] = 0.f;
        g_psumsq[b][col] = 0.f;
    }
    sh1[grp][col] = s;
    sh2[grp][col] = s2;
    __syncthreads();
    if (grp == 0) {
        float ts = 0.f, ts2 = 0.f;
#pragma unroll
        for (int g = 0; g < 8; g++) { ts += sh1[g][col]; ts2 += sh2[g][col]; }
        float mean = ts * invN;
        float var  = fmaf(-mean, mean, ts2 * invN);
        float sc   = gamma[col] * rsqrtf(var + 1e-5f);
        g_scale[col] = sc;
        g_shift[col] = fmaf(-mean, sc, beta[col]);
    }
}

// ---------------- launch -----------------------------------------------------
extern "C" void kernel_launch(void* const* d_in, const int* in_sizes, int n_in,
                              void* d_out, int out_size) {
    const float* x   = (const float*)d_in[0];
    const int*   ei  = (const int*)d_in[1];     // int32 (JAX x64 disabled)
    const float* ew  = (const float*)d_in[2];
    const float* W1  = (const float*)d_in[3];
    const float* b1  = (const float*)d_in[4];
    const float* ga1 = (const float*)d_in[5];
    const float* be1 = (const float*)d_in[6];
    const float* W2  = (const float*)d_in[7];
    const float* b2  = (const float*)d_in[8];
    const float* ga2 = (const float*)d_in[9];
    const float* be2 = (const float*)d_in[10];
    const float* W3  = (const float*)d_in[11];
    const float* b3  = (const float*)d_in[12];
    float* out = (float*)d_out;

    int N = in_sizes[0] / FDIM;
    int E = in_sizes[2];

    const int TB = 256;
    int gbN  = (N + TB - 1) / TB;
    int gbE  = (E + TB - 1) / TB;
    int gbM  = (N + 127) / 128;
    int gbG  = (N + 7) / 8;                 // gather: 8 nodes / 256-thread block
    int gbNW = (N * 32 + TB - 1) / TB;      // warp-per-node

    // ---- graph preprocessing + CSR build (4 kernels) ----
    k_zero     <<<gbN, TB>>>(N);
    k_deg_cnt  <<<gbE, TB>>>(ei, ew, E, N);
    k_scan_dinv<<<1, SCAN_T>>>(N);
    k_csr_build<<<gbE, TB>>>(ei, ew, E, N);

    // ---- layer 1 ----
    k_gemm128  <<<gbM, 256>>>(x, 0, W1, N);
    k_gather128<<<gbG, 256>>>(b1, N);
    k_bn_reduce<<<1, 1024>>>(ga1, be1, 1.0f / (float)N);

    // ---- layer 2 (BN1+relu fused into gemm A-load) ----
    k_gemm128  <<<gbM, 256>>>(x, 1, W2, N);
    k_gather128<<<gbG, 256>>>(b2, N);
    k_bn_reduce<<<1, 1024>>>(ga2, be2, 1.0f / (float)N);

    // ---- layer 3 (BN2+relu fused) + log_softmax ----
    k_gemm40       <<<gbM, 256>>>(W3, N);
    k_gather40_lsm <<<gbNW, TB>>>(b3, out, N);
}

// round 10
// speedup vs baseline: 1.9904x; 1.0046x over previous
#include <cuda_runtime.h>
#include <cstdint>

#define NMAX 50000
#define EMAX 800000
#define FDIM 128
#define CDIM 40
#define SCAN_T 1024
#define STATS_B 512

// ---------------- device scratch (static allocation; no cudaMalloc) ----------
__device__ float g_xw [NMAX * FDIM];   // GEMM output of current layer
__device__ float g_h  [NMAX * FDIM];   // aggregated hidden state (pre-BN)
__device__ float g_xw3[NMAX * CDIM];   // layer-3 GEMM output
__device__ float g_deg [NMAX];         // edge-weight in-degree (without self loop)
__device__ float g_dinv[NMAX];
__device__ int   g_cnt   [NMAX];       // in-degree counts
__device__ int   g_rowptr[NMAX + 1];   // CSR row pointers (by dst)
__device__ int   g_cursor[NMAX];       // fill cursors
__device__ int2  g_csr   [EMAX];       // packed {src, bitcast(norm)}
__device__ float g_psum  [STATS_B][FDIM];   // BN partial sums   (zero-invariant:
__device__ float g_psumsq[STATS_B][FDIM];   //  bn_reduce re-zeroes after reading)
__device__ float g_scale[FDIM];
__device__ float g_shift[FDIM];

// ---------------- graph preprocessing ----------------------------------------
// edge_index is int32 (JAX x64 disabled downcasts jnp.int64 -> int32).
__global__ void k_zero(int N) {
    int i = blockIdx.x * blockDim.x + threadIdx.x;
    if (i < N) { g_deg[i] = 0.f; g_cnt[i] = 0; }
}

__global__ void k_deg_cnt(const int* __restrict__ ei,
                          const float* __restrict__ ew, int E, int N) {
    int e = blockIdx.x * blockDim.x + threadIdx.x;
    if (e >= E) return;
    int d = ei[E + e];
    if ((unsigned)d < (unsigned)N) {
        atomicAdd(&g_deg[d], ew[e]);
        atomicAdd(&g_cnt[d], 1);
    }
}

// dinv prologue + single-block exclusive scan over counts -> rowptr + cursor
__global__ void k_scan_dinv(int N) {
    __shared__ int sh[SCAN_T];
    int tid = threadIdx.x;
    for (int i = tid; i < N; i += SCAN_T)
        g_dinv[i] = rsqrtf(g_deg[i] + 1.0f);   // +1 = self-loop weight
    __syncthreads();
    int chunk = (N + SCAN_T - 1) / SCAN_T;
    int start = tid * chunk;
    int end   = min(start + chunk, N);
    int sum = 0;
    for (int i = start; i < end; i++) sum += g_cnt[i];
    sh[tid] = sum;
    __syncthreads();
    for (int off = 1; off < SCAN_T; off <<= 1) {
        int v = (tid >= off) ? sh[tid - off] : 0;
        __syncthreads();
        sh[tid] += v;
        __syncthreads();
    }
    int off = sh[tid] - sum;   // exclusive prefix
    for (int i = start; i < end; i++) {
        g_rowptr[i] = off;
        g_cursor[i] = off;
        off += g_cnt[i];
    }
    if (tid == SCAN_T - 1) g_rowptr[N] = off;
}

// norm compute + CSR fill in one pass
__global__ void k_csr_build(const int* __restrict__ ei,
                            const float* __restrict__ ew, int E, int N) {
    int e = blockIdx.x * blockDim.x + threadIdx.x;
    if (e >= E) return;
    int s = ei[e];
    int d = ei[E + e];
    if ((unsigned)s >= (unsigned)N) s = 0;
    if ((unsigned)d >= (unsigned)N) d = 0;
    float nrm = g_dinv[s] * ew[e] * g_dinv[d];
    int pos = atomicAdd(&g_cursor[d], 1);
    g_csr[pos] = make_int2(s, __float_as_int(nrm));
}

// ---------------- split-precision TF32 helpers --------------------------------
__device__ __forceinline__ void split_tf32(float x, float& hi, float& lo) {
    uint32_t h;
    asm("cvt.rna.tf32.f32 %0, %1;" : "=r"(h) : "f"(x));
    hi = __uint_as_float(h);
    lo = x - hi;
}

__device__ __forceinline__ void mma_tf32(float* c, const uint32_t* a,
                                         uint32_t b0, uint32_t b1) {
    asm("mma.sync.aligned.m16n8k8.row.col.f32.tf32.tf32.f32 "
        "{%0,%1,%2,%3}, {%4,%5,%6,%7}, {%8,%9}, {%0,%1,%2,%3};"
        : "+f"(c[0]), "+f"(c[1]), "+f"(c[2]), "+f"(c[3])
        : "r"(a[0]), "r"(a[1]), "r"(a[2]), "r"(a[3]), "r"(b0), "r"(b1));
}

// ---------------- TF32 split GEMM: [M,128] @ [128,128] ------------------------
// D = A@B via (hi+lo) x (hi+lo), dropping lo*lo: fp32-class accuracy (~2^-21).
// bnsel: 0 -> A = external x; 1 -> A = relu(g_h*scale + shift) fused on load.
// Block 256 thr = 8 warps (4 m-slices x 2 n-slices), block tile 128x128,
// warp tile 32x64 (2 m16-tiles x 8 n8-tiles), K chunked by 16 through smem.
#define KC 16
#define KPAD 17
__global__ __launch_bounds__(256) void k_gemm128_tf32(const float* __restrict__ Aext,
                                                      int bnsel,
                                                      const float* __restrict__ B,
                                                      int M) {
    const float* __restrict__ A = bnsel ? (const float*)g_h : Aext;
    __shared__ float As_hi[128][KPAD];
    __shared__ float As_lo[128][KPAD];
    __shared__ float Bs_hi[128][KPAD];   // [n][k] (transposed on store)
    __shared__ float Bs_lo[128][KPAD];

    const int tid    = threadIdx.x;
    const int lane   = tid & 31;
    const int warp   = tid >> 5;
    const int warp_m = warp & 3;          // 4 x 32 rows
    const int warp_n = warp >> 2;         // 2 x 64 cols
    const int row0   = blockIdx.x * 128;

    // loader mapping (per 16-wide K chunk)
    const int a_row = tid >> 1;           // 0..127
    const int a_k0  = (tid & 1) * 8;      // two float4 = 8 k values
    const int b_k   = tid >> 4;           // 0..15
    const int b_n0  = (tid & 15) * 8;     // 8 n values (2 float4)

    float acc[2][8][4];
#pragma unroll
    for (int mt = 0; mt < 2; mt++)
#pragma unroll
        for (int nt = 0; nt < 8; nt++)
#pragma unroll
            for (int r = 0; r < 4; r++) acc[mt][nt][r] = 0.f;

#pragma unroll 1
    for (int ch = 0; ch < 128 / KC; ch++) {
        const int k0 = ch * KC;
        __syncthreads();   // protect smem from previous iteration's readers

        // ---- stage A chunk (with optional fused BN+ReLU), split hi/lo ----
        {
            int grow = row0 + a_row;
            float v[8];
#pragma unroll
            for (int i = 0; i < 8; i++) v[i] = 0.f;
            if (grow < M) {
                const float* ap = A + (size_t)grow * 128 + k0 + a_k0;
                float4 u0 = *(const float4*)ap;
                float4 u1 = *(const float4*)(ap + 4);
                v[0] = u0.x; v[1] = u0.y; v[2] = u0.z; v[3] = u0.w;
                v[4] = u1.x; v[5] = u1.y; v[6] = u1.z; v[7] = u1.w;
                if (bnsel) {
#pragma unroll
                    for (int i = 0; i < 8; i++) {
                        int c = k0 + a_k0 + i;
                        v[i] = fmaxf(0.f, fmaf(v[i], g_scale[c], g_shift[c]));
                    }
                }
            }
#pragma unroll
            for (int i = 0; i < 8; i++) {
                float hi, lo;
                split_tf32(v[i], hi, lo);
                As_hi[a_row][a_k0 + i] = hi;
                As_lo[a_row][a_k0 + i] = lo;
            }
        }
        // ---- stage B chunk transposed, split hi/lo ----
        {
            const float* bp = B + (size_t)(k0 + b_k) * 128 + b_n0;
            float4 u0 = *(const float4*)bp;
            float4 u1 = *(const float4*)(bp + 4);
            float v[8] = {u0.x, u0.y, u0.z, u0.w, u1.x, u1.y, u1.z, u1.w};
#pragma unroll
            for (int i = 0; i < 8; i++) {
                float hi, lo;
                split_tf32(v[i], hi, lo);
                Bs_hi[b_n0 + i][b_k] = hi;
                Bs_lo[b_n0 + i][b_k] = lo;
            }
        }
        __syncthreads();

        // ---- 2 k8 steps per chunk ----
#pragma unroll
        for (int s = 0; s < KC / 8; s++) {
            const int ac = s * 8 + (lane & 3);
            const int ar = warp_m * 32 + (lane >> 2);
            uint32_t a_hi[2][4], a_lo[2][4];
#pragma unroll
            for (int mt = 0; mt < 2; mt++) {
                int r = ar + mt * 16;
                a_hi[mt][0] = __float_as_uint(As_hi[r    ][ac    ]);
                a_hi[mt][1] = __float_as_uint(As_hi[r + 8][ac    ]);
                a_hi[mt][2] = __float_as_uint(As_hi[r    ][ac + 4]);
                a_hi[mt][3] = __float_as_uint(As_hi[r + 8][ac + 4]);
                a_lo[mt][0] = __float_as_uint(As_lo[r    ][ac    ]);
                a_lo[mt][1] = __float_as_uint(As_lo[r + 8][ac    ]);
                a_lo[mt][2] = __float_as_uint(As_lo[r    ][ac + 4]);
                a_lo[mt][3] = __float_as_uint(As_lo[r + 8][ac + 4]);
            }
            const int bk = s * 8 + (lane & 3);
#pragma unroll
            for (int nt = 0; nt < 8; nt++) {
                int bn = warp_n * 64 + nt * 8 + (lane >> 2);
                uint32_t bh0 = __float_as_uint(Bs_hi[bn][bk]);
                uint32_t bh1 = __float_as_uint(Bs_hi[bn][bk + 4]);
                uint32_t bl0 = __float_as_uint(Bs_lo[bn][bk]);
                uint32_t bl1 = __float_as_uint(Bs_lo[bn][bk + 4]);
#pragma unroll
                for (int mt = 0; mt < 2; mt++) {
                    mma_tf32(acc[mt][nt], a_hi[mt], bh0, bh1);
                    mma_tf32(acc[mt][nt], a_hi[mt], bl0, bl1);
                    mma_tf32(acc[mt][nt], a_lo[mt], bh0, bh1);
                }
            }
        }
    }

    // ---- epilogue: write g_xw ----
#pragma unroll
    for (int mt = 0; mt < 2; mt++) {
        int r0 = row0 + warp_m * 32 + mt * 16 + (lane >> 2);
        int r1 = r0 + 8;
#pragma unroll
        for (int nt = 0; nt < 8; nt++) {
            int col = warp_n * 64 + nt * 8 + (lane & 3) * 2;
            if (r0 < M)
                *(float2*)(g_xw + (size_t)r0 * 128 + col) =
                    make_float2(acc[mt][nt][0], acc[mt][nt][1]);
            if (r1 < M)
                *(float2*)(g_xw + (size_t)r1 * 128 + col) =
                    make_float2(acc[mt][nt][2], acc[mt][nt][3]);
        }
    }
}

// ---------------- SGEMM: [M,128] @ [128,40]  (BN2+relu(g_h) -> g_xw3) ---------
__global__ __launch_bounds__(256) void k_gemm40(const float* __restrict__ B,
                                                int M) {
    __shared__ float As[16][128];
    __shared__ float Bs[16][40];
    const int tid  = threadIdx.x;
    const int tx   = tid & 7;
    const int ty   = tid >> 3;
    const int row0 = blockIdx.x * 128;
    const int a_row = tid >> 1;
    const int a_k4  = (tid & 1) * 8;

    float acc[4][5];
#pragma unroll
    for (int i = 0; i < 4; i++)
#pragma unroll
        for (int j = 0; j < 5; j++) acc[i][j] = 0.f;

#pragma unroll 1
    for (int k0 = 0; k0 < 128; k0 += 16) {
        int grow = row0 + a_row;
        float4 av0 = make_float4(0.f, 0.f, 0.f, 0.f);
        float4 av1 = av0;
        if (grow < M) {
            const float* ap = g_h + (size_t)grow * 128 + k0 + a_k4;
            av0 = *(const float4*)ap;
            av1 = *(const float4*)(ap + 4);
            int c4 = (k0 + a_k4) >> 2;
            float4 sc0 = ((const float4*)g_scale)[c4];
            float4 sc1 = ((const float4*)g_scale)[c4 + 1];
            float4 sh0 = ((const float4*)g_shift)[c4];
            float4 sh1 = ((const float4*)g_shift)[c4 + 1];
            av0.x = fmaxf(0.f, fmaf(av0.x, sc0.x, sh0.x));
            av0.y = fmaxf(0.f, fmaf(av0.y, sc0.y, sh0.y));
            av0.z = fmaxf(0.f, fmaf(av0.z, sc0.z, sh0.z));
            av0.w = fmaxf(0.f, fmaf(av0.w, sc0.w, sh0.w));
            av1.x = fmaxf(0.f, fmaf(av1.x, sc1.x, sh1.x));
            av1.y = fmaxf(0.f, fmaf(av1.y, sc1.y, sh1.y));
            av1.z = fmaxf(0.f, fmaf(av1.z, sc1.z, sh1.z));
            av1.w = fmaxf(0.f, fmaf(av1.w, sc1.w, sh1.w));
        }
        As[a_k4 + 0][a_row] = av0.x; As[a_k4 + 1][a_row] = av0.y;
        As[a_k4 + 2][a_row] = av0.z; As[a_k4 + 3][a_row] = av0.w;
        As[a_k4 + 4][a_row] = av1.x; As[a_k4 + 5][a_row] = av1.y;
        As[a_k4 + 6][a_row] = av1.z; As[a_k4 + 7][a_row] = av1.w;

        for (int i = tid; i < 16 * 40; i += 256) {
            int bk = i / 40, bn = i % 40;
            Bs[bk][bn] = B[(size_t)(k0 + bk) * 40 + bn];
        }
        __syncthreads();

#pragma unroll
        for (int kk = 0; kk < 16; kk++) {
            float ar[4], br[5];
#pragma unroll
            for (int i = 0; i < 4; i++) ar[i] = As[kk][ty * 4 + i];
#pragma unroll
            for (int j = 0; j < 5; j++) br[j] = Bs[kk][tx * 5 + j];
#pragma unroll
            for (int i = 0; i < 4; i++)
#pragma unroll
                for (int j = 0; j < 5; j++)
                    acc[i][j] = fmaf(ar[i], br[j], acc[i][j]);
        }
        __syncthreads();
    }

#pragma unroll
    for (int i = 0; i < 4; i++) {
        int r = row0 + ty * 4 + i;
        if (r < M) {
#pragma unroll
            for (int j = 0; j < 5; j++)
                g_xw3[(size_t)r * 40 + tx * 5 + j] = acc[i][j];
        }
    }
}

// ---------------- CSR gather + fused BN partial stats -------------------------
__global__ __launch_bounds__(256) void k_gather128(const float* __restrict__ b,
                                                   int N) {
    __shared__ float4 sh_s [8][32];
    __shared__ float4 sh_s2[8][32];
    const int warp = threadIdx.x >> 5;
    const int lane = threadIdx.x & 31;
    const int n = blockIdx.x * 8 + warp;

    float4 a0 = make_float4(0.f, 0.f, 0.f, 0.f);
    float4 a1 = a0, a2 = a0, a3 = a0;

    if (n < N) {
        float di = g_dinv[n]; di *= di;
        float4 bv = ((const float4*)b)[lane];
        float4 xv = ((const float4*)g_xw)[(size_t)n * 32 + lane];
        a0.x = fmaf(di, xv.x, bv.x); a0.y = fmaf(di, xv.y, bv.y);
        a0.z = fmaf(di, xv.z, bv.z); a0.w = fmaf(di, xv.w, bv.w);

        int j   = g_rowptr[n];
        int end = g_rowptr[n + 1];
        for (; j + 3 < end; j += 4) {
            int2 e0 = g_csr[j],     e1 = g_csr[j + 1];
            int2 e2 = g_csr[j + 2], e3 = g_csr[j + 3];
            float4 v0 = ((const float4*)g_xw)[(size_t)e0.x * 32 + lane];
            float4 v1 = ((const float4*)g_xw)[(size_t)e1.x * 32 + lane];
            float4 v2 = ((const float4*)g_xw)[(size_t)e2.x * 32 + lane];
            float4 v3 = ((const float4*)g_xw)[(size_t)e3.x * 32 + lane];
            float w0 = __int_as_float(e0.y), w1 = __int_as_float(e1.y);
            float w2 = __int_as_float(e2.y), w3 = __int_as_float(e3.y);
            a0.x = fmaf(w0, v0.x, a0.x); a0.y = fmaf(w0, v0.y, a0.y);
            a0.z = fmaf(w0, v0.z, a0.z); a0.w = fmaf(w0, v0.w, a0.w);
            a1.x = fmaf(w1, v1.x, a1.x); a1.y = fmaf(w1, v1.y, a1.y);
            a1.z = fmaf(w1, v1.z, a1.z); a1.w = fmaf(w1, v1.w, a1.w);
            a2.x = fmaf(w2, v2.x, a2.x); a2.y = fmaf(w2, v2.y, a2.y);
            a2.z = fmaf(w2, v2.z, a2.z); a2.w = fmaf(w2, v2.w, a2.w);
            a3.x = fmaf(w3, v3.x, a3.x); a3.y = fmaf(w3, v3.y, a3.y);
            a3.z = fmaf(w3, v3.z, a3.z); a3.w = fmaf(w3, v3.w, a3.w);
        }
        for (; j < end; j++) {
            int2 e = g_csr[j];
            float4 v = ((const float4*)g_xw)[(size_t)e.x * 32 + lane];
            float w = __int_as_float(e.y);
            a0.x = fmaf(w, v.x, a0.x); a0.y = fmaf(w, v.y, a0.y);
            a0.z = fmaf(w, v.z, a0.z); a0.w = fmaf(w, v.w, a0.w);
        }
        a0.x = (a0.x + a1.x) + (a2.x + a3.x);
        a0.y = (a0.y + a1.y) + (a2.y + a3.y);
        a0.z = (a0.z + a1.z) + (a2.z + a3.z);
        a0.w = (a0.w + a1.w) + (a2.w + a3.w);
        ((float4*)g_h)[(size_t)n * 32 + lane] = a0;
    } else {
        a0 = make_float4(0.f, 0.f, 0.f, 0.f);
    }

    sh_s [warp][lane] = a0;
    sh_s2[warp][lane] = make_float4(a0.x * a0.x, a0.y * a0.y,
                                    a0.z * a0.z, a0.w * a0.w);
    __syncthreads();
    if (warp == 0) {
        float4 ts  = make_float4(0.f, 0.f, 0.f, 0.f);
        float4 ts2 = ts;
#pragma unroll
        for (int g = 0; g < 8; g++) {
            float4 s  = sh_s [g][lane];
            float4 s2 = sh_s2[g][lane];
            ts.x += s.x;  ts.y += s.y;  ts.z += s.z;  ts.w += s.w;
            ts2.x += s2.x; ts2.y += s2.y; ts2.z += s2.z; ts2.w += s2.w;
        }
        int slot = blockIdx.x & (STATS_B - 1);
        float* ps  = &g_psum  [slot][lane * 4];
        float* ps2 = &g_psumsq[slot][lane * 4];
        atomicAdd(ps + 0, ts.x);  atomicAdd(ps + 1, ts.y);
        atomicAdd(ps + 2, ts.z);  atomicAdd(ps + 3, ts.w);
        atomicAdd(ps2 + 0, ts2.x); atomicAdd(ps2 + 1, ts2.y);
        atomicAdd(ps2 + 2, ts2.z); atomicAdd(ps2 + 3, ts2.w);
    }
}

// layer 3: gather + bias + self-loop + log_softmax, one warp per node
__global__ void k_gather40_lsm(const float* __restrict__ b3,
                               float* __restrict__ out, int N) {
    int t = blockIdx.x * blockDim.x + threadIdx.x;
    int n = t >> 5, lane = t & 31;
    if (n >= N) return;
    float di = g_dinv[n]; di *= di;
    const float* xr = g_xw3 + (size_t)n * 40;
    float v1 = fmaf(di, xr[lane], b3[lane]);
    float v2 = (lane < 8) ? fmaf(di, xr[32 + lane], b3[32 + lane]) : 0.f;
    int j   = g_rowptr[n];
    int end = g_rowptr[n + 1];
    for (; j < end; j++) {
        int2 e = g_csr[j];
        float w = __int_as_float(e.y);
        const float* sr = g_xw3 + (size_t)e.x * 40;
        v1 = fmaf(w, sr[lane], v1);
        if (lane < 8) v2 = fmaf(w, sr[32 + lane], v2);
    }
    float m = (lane < 8) ? fmaxf(v1, v2) : v1;
#pragma unroll
    for (int o = 16; o > 0; o >>= 1) m = fmaxf(m, __shfl_xor_sync(0xffffffffu, m, o));
    float s = expf(v1 - m) + ((lane < 8) ? expf(v2 - m) : 0.f);
#pragma unroll
    for (int o = 16; o > 0; o >>= 1) s += __shfl_xor_sync(0xffffffffu, s, o);
    float l = m + logf(s);
    float* p = out + (size_t)n * 40;
    p[lane] = v1 - l;
    if (lane < 8) p[32 + lane] = v2 - l;
}

// ---------------- batch norm reduce (also re-zeroes partials) -----------------
__global__ void k_bn_reduce(const float* __restrict__ gamma,
                            const float* __restrict__ beta, float invN) {
    __shared__ float sh1[8][FDIM];
    __shared__ float sh2[8][FDIM];
    int col = threadIdx.x & 127;
    int grp = threadIdx.x >> 7;       // 0..7
    float s = 0.f, s2 = 0.f;
    for (int b = grp * (STATS_B / 8); b < (grp + 1) * (STATS_B / 8); b++) {
        s  += g_psum  [b][col];
        s2 += g_psumsq[b][col];
        g_psum  [b][col] = 0.f;
        g_psumsq[b][col] = 0.f;
    }
    sh1[grp][col] = s;
    sh2[grp][col] = s2;
    __syncthreads();
    if (grp == 0) {
        float ts = 0.f, ts2 = 0.f;
#pragma unroll
        for (int g = 0; g < 8; g++) { ts += sh1[g][col]; ts2 += sh2[g][col]; }
        float mean = ts * invN;
        float var  = fmaf(-mean, mean, ts2 * invN);
        float sc   = gamma[col] * rsqrtf(var + 1e-5f);
        g_scale[col] = sc;
        g_shift[col] = fmaf(-mean, sc, beta[col]);
    }
}

// ---------------- launch -----------------------------------------------------
extern "C" void kernel_launch(void* const* d_in, const int* in_sizes, int n_in,
                              void* d_out, int out_size) {
    const float* x   = (const float*)d_in[0];
    const int*   ei  = (const int*)d_in[1];     // int32 (JAX x64 disabled)
    const float* ew  = (const float*)d_in[2];
    const float* W1  = (const float*)d_in[3];
    const float* b1  = (const float*)d_in[4];
    const float* ga1 = (const float*)d_in[5];
    const float* be1 = (const float*)d_in[6];
    const float* W2  = (const float*)d_in[7];
    const float* b2  = (const float*)d_in[8];
    const float* ga2 = (const float*)d_in[9];
    const float* be2 = (const float*)d_in[10];
    const float* W3  = (const float*)d_in[11];
    const float* b3  = (const float*)d_in[12];
    float* out = (float*)d_out;

    int N = in_sizes[0] / FDIM;
    int E = in_sizes[2];

    const int TB = 256;
    int gbN  = (N + TB - 1) / TB;
    int gbE  = (E + TB - 1) / TB;
    int gbM  = (N + 127) / 128;
    int gbG  = (N + 7) / 8;                 // gather: 8 nodes / 256-thread block
    int gbNW = (N * 32 + TB - 1) / TB;      // warp-per-node

    // ---- graph preprocessing + CSR build (4 kernels) ----
    k_zero     <<<gbN, TB>>>(N);
    k_deg_cnt  <<<gbE, TB>>>(ei, ew, E, N);
    k_scan_dinv<<<1, SCAN_T>>>(N);
    k_csr_build<<<gbE, TB>>>(ei, ew, E, N);

    // ---- layer 1 ----
    k_gemm128_tf32<<<gbM, 256>>>(x, 0, W1, N);
    k_gather128   <<<gbG, 256>>>(b1, N);
    k_bn_reduce   <<<1, 1024>>>(ga1, be1, 1.0f / (float)N);

    // ---- layer 2 (BN1+relu fused into gemm A-load) ----
    k_gemm128_tf32<<<gbM, 256>>>(x, 1, W2, N);
    k_gather128   <<<gbG, 256>>>(b2, N);
    k_bn_reduce   <<<1, 1024>>>(ga2, be2, 1.0f / (float)N);

    // ---- layer 3 (BN2+relu fused) + log_softmax ----
    k_gemm40       <<<gbM, 256>>>(W3, N);
    k_gather40_lsm <<<gbNW, TB>>>(b3, out, N);
}

// round 11
// speedup vs baseline: 2.0536x; 1.0317x over previous
#include <cuda_runtime.h>
#include <cstdint>

#define NMAX 50000
#define EMAX 800000
#define FDIM 128
#define CDIM 40
#define SCAN_T 1024
#define STATS_B 512

// ---------------- device scratch (static allocation; no cudaMalloc) ----------
__device__ float g_xw [NMAX * FDIM];   // GEMM output of current layer
__device__ float g_h  [NMAX * FDIM];   // aggregated hidden state (pre-BN)
__device__ float g_xw3[NMAX * CDIM];   // layer-3 GEMM output
__device__ float g_deg [NMAX];         // edge-weight in-degree (without self loop)
__device__ float g_dinv[NMAX];
__device__ int   g_cnt   [NMAX];       // in-degree counts
__device__ int   g_rowptr[NMAX + 1];   // CSR row pointers (by dst)
__device__ int   g_cursor[NMAX];       // fill cursors
__device__ int2  g_csr   [EMAX];       // packed {src, bitcast(norm)}
__device__ float g_psum  [STATS_B][FDIM];   // BN partial sums   (zero-invariant:
__device__ float g_psumsq[STATS_B][FDIM];   //  bn_reduce re-zeroes after reading)
__device__ float g_scale[FDIM];
__device__ float g_shift[FDIM];

// ---------------- graph preprocessing ----------------------------------------
// edge_index is int32 (JAX x64 disabled downcasts jnp.int64 -> int32).
__global__ void k_zero(int N) {
    int i = blockIdx.x * blockDim.x + threadIdx.x;
    if (i < N) { g_deg[i] = 0.f; g_cnt[i] = 0; }
}

__global__ void k_deg_cnt(const int* __restrict__ ei,
                          const float* __restrict__ ew, int E, int N) {
    int e = blockIdx.x * blockDim.x + threadIdx.x;
    if (e >= E) return;
    int d = ei[E + e];
    if ((unsigned)d < (unsigned)N) {
        atomicAdd(&g_deg[d], ew[e]);
        atomicAdd(&g_cnt[d], 1);
    }
}

// grid-wide dinv (was a 1-block prologue of the scan — single-SM bound)
__global__ void k_dinv(int N) {
    int i = blockIdx.x * blockDim.x + threadIdx.x;
    if (i < N) g_dinv[i] = rsqrtf(g_deg[i] + 1.0f);   // +1 = self-loop weight
}

// single-block exclusive scan over counts -> rowptr + cursor
__global__ void k_scan(int N) {
    __shared__ int sh[SCAN_T];
    int tid = threadIdx.x;
    int chunk = (N + SCAN_T - 1) / SCAN_T;
    int start = tid * chunk;
    int end   = min(start + chunk, N);
    int sum = 0;
    for (int i = start; i < end; i++) sum += g_cnt[i];
    sh[tid] = sum;
    __syncthreads();
    for (int off = 1; off < SCAN_T; off <<= 1) {
        int v = (tid >= off) ? sh[tid - off] : 0;
        __syncthreads();
        sh[tid] += v;
        __syncthreads();
    }
    int off = sh[tid] - sum;   // exclusive prefix
    for (int i = start; i < end; i++) {
        g_rowptr[i] = off;
        g_cursor[i] = off;
        off += g_cnt[i];
    }
    if (tid == SCAN_T - 1) g_rowptr[N] = off;
}

// norm compute + CSR fill in one pass
__global__ void k_csr_build(const int* __restrict__ ei,
                            const float* __restrict__ ew, int E, int N) {
    int e = blockIdx.x * blockDim.x + threadIdx.x;
    if (e >= E) return;
    int s = ei[e];
    int d = ei[E + e];
    if ((unsigned)s >= (unsigned)N) s = 0;
    if ((unsigned)d >= (unsigned)N) d = 0;
    float nrm = g_dinv[s] * ew[e] * g_dinv[d];
    int pos = atomicAdd(&g_cursor[d], 1);
    g_csr[pos] = make_int2(s, __float_as_int(nrm));
}

// ---------------- split-precision TF32 helpers --------------------------------
__device__ __forceinline__ void split_tf32(float x, float& hi, float& lo) {
    uint32_t h;
    asm("cvt.rna.tf32.f32 %0, %1;" : "=r"(h) : "f"(x));
    hi = __uint_as_float(h);
    lo = x - hi;
}

__device__ __forceinline__ void mma_tf32(float* c, const uint32_t* a,
                                         uint32_t b0, uint32_t b1) {
    asm("mma.sync.aligned.m16n8k8.row.col.f32.tf32.tf32.f32 "
        "{%0,%1,%2,%3}, {%4,%5,%6,%7}, {%8,%9}, {%0,%1,%2,%3};"
        : "+f"(c[0]), "+f"(c[1]), "+f"(c[2]), "+f"(c[3])
        : "r"(a[0]), "r"(a[1]), "r"(a[2]), "r"(a[3]), "r"(b0), "r"(b1));
}

// ---------------- TF32 split GEMM: [M,128] @ [128,128] ------------------------
// D = A@B via (hi+lo) x (hi+lo), dropping lo*lo: fp32-class accuracy (~2^-21).
// bnsel: 0 -> A = external x; 1 -> A = relu(g_h*scale + shift) fused on load.
#define KC 16
#define KPAD 17
__global__ __launch_bounds__(256) void k_gemm128_tf32(const float* __restrict__ Aext,
                                                      int bnsel,
                                                      const float* __restrict__ B,
                                                      int M) {
    const float* __restrict__ A = bnsel ? (const float*)g_h : Aext;
    __shared__ float As_hi[128][KPAD];
    __shared__ float As_lo[128][KPAD];
    __shared__ float Bs_hi[128][KPAD];   // [n][k] (transposed on store)
    __shared__ float Bs_lo[128][KPAD];

    const int tid    = threadIdx.x;
    const int lane   = tid & 31;
    const int warp   = tid >> 5;
    const int warp_m = warp & 3;          // 4 x 32 rows
    const int warp_n = warp >> 2;         // 2 x 64 cols
    const int row0   = blockIdx.x * 128;

    // loader mapping (per 16-wide K chunk)
    const int a_row = tid >> 1;           // 0..127
    const int a_k0  = (tid & 1) * 8;      // two float4 = 8 k values
    const int b_k   = tid >> 4;           // 0..15
    const int b_n0  = (tid & 15) * 8;     // 8 n values (2 float4)

    float acc[2][8][4];
#pragma unroll
    for (int mt = 0; mt < 2; mt++)
#pragma unroll
        for (int nt = 0; nt < 8; nt++)
#pragma unroll
            for (int r = 0; r < 4; r++) acc[mt][nt][r] = 0.f;

#pragma unroll 1
    for (int ch = 0; ch < 128 / KC; ch++) {
        const int k0 = ch * KC;
        __syncthreads();   // protect smem from previous iteration's readers

        // ---- stage A chunk (with optional fused BN+ReLU), split hi/lo ----
        {
            int grow = row0 + a_row;
            float v[8];
#pragma unroll
            for (int i = 0; i < 8; i++) v[i] = 0.f;
            if (grow < M) {
                const float* ap = A + (size_t)grow * 128 + k0 + a_k0;
                float4 u0 = *(const float4*)ap;
                float4 u1 = *(const float4*)(ap + 4);
                v[0] = u0.x; v[1] = u0.y; v[2] = u0.z; v[3] = u0.w;
                v[4] = u1.x; v[5] = u1.y; v[6] = u1.z; v[7] = u1.w;
                if (bnsel) {
#pragma unroll
                    for (int i = 0; i < 8; i++) {
                        int c = k0 + a_k0 + i;
                        v[i] = fmaxf(0.f, fmaf(v[i], g_scale[c], g_shift[c]));
                    }
                }
            }
#pragma unroll
            for (int i = 0; i < 8; i++) {
                float hi, lo;
                split_tf32(v[i], hi, lo);
                As_hi[a_row][a_k0 + i] = hi;
                As_lo[a_row][a_k0 + i] = lo;
            }
        }
        // ---- stage B chunk transposed, split hi/lo ----
        {
            const float* bp = B + (size_t)(k0 + b_k) * 128 + b_n0;
            float4 u0 = *(const float4*)bp;
            float4 u1 = *(const float4*)(bp + 4);
            float v[8] = {u0.x, u0.y, u0.z, u0.w, u1.x, u1.y, u1.z, u1.w};
#pragma unroll
            for (int i = 0; i < 8; i++) {
                float hi, lo;
                split_tf32(v[i], hi, lo);
                Bs_hi[b_n0 + i][b_k] = hi;
                Bs_lo[b_n0 + i][b_k] = lo;
            }
        }
        __syncthreads();

        // ---- 2 k8 steps per chunk ----
#pragma unroll
        for (int s = 0; s < KC / 8; s++) {
            const int ac = s * 8 + (lane & 3);
            const int ar = warp_m * 32 + (lane >> 2);
            uint32_t a_hi[2][4], a_lo[2][4];
#pragma unroll
            for (int mt = 0; mt < 2; mt++) {
                int r = ar + mt * 16;
                a_hi[mt][0] = __float_as_uint(As_hi[r    ][ac    ]);
                a_hi[mt][1] = __float_as_uint(As_hi[r + 8][ac    ]);
                a_hi[mt][2] = __float_as_uint(As_hi[r    ][ac + 4]);
                a_hi[mt][3] = __float_as_uint(As_hi[r + 8][ac + 4]);
                a_lo[mt][0] = __float_as_uint(As_lo[r    ][ac    ]);
                a_lo[mt][1] = __float_as_uint(As_lo[r + 8][ac    ]);
                a_lo[mt][2] = __float_as_uint(As_lo[r    ][ac + 4]);
                a_lo[mt][3] = __float_as_uint(As_lo[r + 8][ac + 4]);
            }
            const int bk = s * 8 + (lane & 3);
#pragma unroll
            for (int nt = 0; nt < 8; nt++) {
                int bn = warp_n * 64 + nt * 8 + (lane >> 2);
                uint32_t bh0 = __float_as_uint(Bs_hi[bn][bk]);
                uint32_t bh1 = __float_as_uint(Bs_hi[bn][bk + 4]);
                uint32_t bl0 = __float_as_uint(Bs_lo[bn][bk]);
                uint32_t bl1 = __float_as_uint(Bs_lo[bn][bk + 4]);
#pragma unroll
                for (int mt = 0; mt < 2; mt++) {
                    mma_tf32(acc[mt][nt], a_hi[mt], bh0, bh1);
                    mma_tf32(acc[mt][nt], a_hi[mt], bl0, bl1);
                    mma_tf32(acc[mt][nt], a_lo[mt], bh0, bh1);
                }
            }
        }
    }

    // ---- epilogue: write g_xw ----
#pragma unroll
    for (int mt = 0; mt < 2; mt++) {
        int r0 = row0 + warp_m * 32 + mt * 16 + (lane >> 2);
        int r1 = r0 + 8;
#pragma unroll
        for (int nt = 0; nt < 8; nt++) {
            int col = warp_n * 64 + nt * 8 + (lane & 3) * 2;
            if (r0 < M)
                *(float2*)(g_xw + (size_t)r0 * 128 + col) =
                    make_float2(acc[mt][nt][0], acc[mt][nt][1]);
            if (r1 < M)
                *(float2*)(g_xw + (size_t)r1 * 128 + col) =
                    make_float2(acc[mt][nt][2], acc[mt][nt][3]);
        }
    }
}

// ---------------- SGEMM: [M,128] @ [128,40]  (BN2+relu(g_h) -> g_xw3) ---------
__global__ __launch_bounds__(256) void k_gemm40(const float* __restrict__ B,
                                                int M) {
    __shared__ float As[16][128];
    __shared__ float Bs[16][40];
    const int tid  = threadIdx.x;
    const int tx   = tid & 7;
    const int ty   = tid >> 3;
    const int row0 = blockIdx.x * 128;
    const int a_row = tid >> 1;
    const int a_k4  = (tid & 1) * 8;

    float acc[4][5];
#pragma unroll
    for (int i = 0; i < 4; i++)
#pragma unroll
        for (int j = 0; j < 5; j++) acc[i][j] = 0.f;

#pragma unroll 1
    for (int k0 = 0; k0 < 128; k0 += 16) {
        int grow = row0 + a_row;
        float4 av0 = make_float4(0.f, 0.f, 0.f, 0.f);
        float4 av1 = av0;
        if (grow < M) {
            const float* ap = g_h + (size_t)grow * 128 + k0 + a_k4;
            av0 = *(const float4*)ap;
            av1 = *(const float4*)(ap + 4);
            int c4 = (k0 + a_k4) >> 2;
            float4 sc0 = ((const float4*)g_scale)[c4];
            float4 sc1 = ((const float4*)g_scale)[c4 + 1];
            float4 sh0 = ((const float4*)g_shift)[c4];
            float4 sh1 = ((const float4*)g_shift)[c4 + 1];
            av0.x = fmaxf(0.f, fmaf(av0.x, sc0.x, sh0.x));
            av0.y = fmaxf(0.f, fmaf(av0.y, sc0.y, sh0.y));
            av0.z = fmaxf(0.f, fmaf(av0.z, sc0.z, sh0.z));
            av0.w = fmaxf(0.f, fmaf(av0.w, sc0.w, sh0.w));
            av1.x = fmaxf(0.f, fmaf(av1.x, sc1.x, sh1.x));
            av1.y = fmaxf(0.f, fmaf(av1.y, sc1.y, sh1.y));
            av1.z = fmaxf(0.f, fmaf(av1.z, sc1.z, sh1.z));
            av1.w = fmaxf(0.f, fmaf(av1.w, sc1.w, sh1.w));
        }
        As[a_k4 + 0][a_row] = av0.x; As[a_k4 + 1][a_row] = av0.y;
        As[a_k4 + 2][a_row] = av0.z; As[a_k4 + 3][a_row] = av0.w;
        As[a_k4 + 4][a_row] = av1.x; As[a_k4 + 5][a_row] = av1.y;
        As[a_k4 + 6][a_row] = av1.z; As[a_k4 + 7][a_row] = av1.w;

        for (int i = tid; i < 16 * 40; i += 256) {
            int bk = i / 40, bn = i % 40;
            Bs[bk][bn] = B[(size_t)(k0 + bk) * 40 + bn];
        }
        __syncthreads();

#pragma unroll
        for (int kk = 0; kk < 16; kk++) {
            float ar[4], br[5];
#pragma unroll
            for (int i = 0; i < 4; i++) ar[i] = As[kk][ty * 4 + i];
#pragma unroll
            for (int j = 0; j < 5; j++) br[j] = Bs[kk][tx * 5 + j];
#pragma unroll
            for (int i = 0; i < 4; i++)
#pragma unroll
                for (int j = 0; j < 5; j++)
                    acc[i][j] = fmaf(ar[i], br[j], acc[i][j]);
        }
        __syncthreads();
    }

#pragma unroll
    for (int i = 0; i < 4; i++) {
        int r = row0 + ty * 4 + i;
        if (r < M) {
#pragma unroll
            for (int j = 0; j < 5; j++)
                g_xw3[(size_t)r * 40 + tx * 5 + j] = acc[i][j];
        }
    }
}

// ---------------- CSR gather + fused BN partial stats -------------------------
// 8-edge unroll: 8 float4 loads in flight per warp (MLP=8) against L2 latency.
__global__ __launch_bounds__(256) void k_gather128(const float* __restrict__ b,
                                                   int N) {
    __shared__ float4 sh_s [8][32];
    __shared__ float4 sh_s2[8][32];
    const int warp = threadIdx.x >> 5;
    const int lane = threadIdx.x & 31;
    const int n = blockIdx.x * 8 + warp;

    float4 a0 = make_float4(0.f, 0.f, 0.f, 0.f);
    float4 a1 = a0, a2 = a0, a3 = a0;

    if (n < N) {
        float di = g_dinv[n]; di *= di;
        float4 bv = ((const float4*)b)[lane];
        float4 xv = ((const float4*)g_xw)[(size_t)n * 32 + lane];
        a0.x = fmaf(di, xv.x, bv.x); a0.y = fmaf(di, xv.y, bv.y);
        a0.z = fmaf(di, xv.z, bv.z); a0.w = fmaf(di, xv.w, bv.w);

        int j   = g_rowptr[n];
        int end = g_rowptr[n + 1];
        for (; j + 7 < end; j += 8) {      // MLP=8
            int2 e0 = g_csr[j],     e1 = g_csr[j + 1];
            int2 e2 = g_csr[j + 2], e3 = g_csr[j + 3];
            int2 e4 = g_csr[j + 4], e5 = g_csr[j + 5];
            int2 e6 = g_csr[j + 6], e7 = g_csr[j + 7];
            float4 v0 = ((const float4*)g_xw)[(size_t)e0.x * 32 + lane];
            float4 v1 = ((const float4*)g_xw)[(size_t)e1.x * 32 + lane];
            float4 v2 = ((const float4*)g_xw)[(size_t)e2.x * 32 + lane];
            float4 v3 = ((const float4*)g_xw)[(size_t)e3.x * 32 + lane];
            float4 v4 = ((const float4*)g_xw)[(size_t)e4.x * 32 + lane];
            float4 v5 = ((const float4*)g_xw)[(size_t)e5.x * 32 + lane];
            float4 v6 = ((const float4*)g_xw)[(size_t)e6.x * 32 + lane];
            float4 v7 = ((const float4*)g_xw)[(size_t)e7.x * 32 + lane];
            float w0 = __int_as_float(e0.y), w1 = __int_as_float(e1.y);
            float w2 = __int_as_float(e2.y), w3 = __int_as_float(e3.y);
            float w4 = __int_as_float(e4.y), w5 = __int_as_float(e5.y);
            float w6 = __int_as_float(e6.y), w7 = __int_as_float(e7.y);
            a0.x = fmaf(w0, v0.x, a0.x); a0.y = fmaf(w0, v0.y, a0.y);
            a0.z = fmaf(w0, v0.z, a0.z); a0.w = fmaf(w0, v0.w, a0.w);
            a1.x = fmaf(w1, v1.x, a1.x); a1.y = fmaf(w1, v1.y, a1.y);
            a1.z = fmaf(w1, v1.z, a1.z); a1.w = fmaf(w1, v1.w, a1.w);
            a2.x = fmaf(w2, v2.x, a2.x); a2.y = fmaf(w2, v2.y, a2.y);
            a2.z = fmaf(w2, v2.z, a2.z); a2.w = fmaf(w2, v2.w, a2.w);
            a3.x = fmaf(w3, v3.x, a3.x); a3.y = fmaf(w3, v3.y, a3.y);
            a3.z = fmaf(w3, v3.z, a3.z); a3.w = fmaf(w3, v3.w, a3.w);
            a0.x = fmaf(w4, v4.x, a0.x); a0.y = fmaf(w4, v4.y, a0.y);
            a0.z = fmaf(w4, v4.z, a0.z); a0.w = fmaf(w4, v4.w, a0.w);
            a1.x = fmaf(w5, v5.x, a1.x); a1.y = fmaf(w5, v5.y, a1.y);
            a1.z = fmaf(w5, v5.z, a1.z); a1.w = fmaf(w5, v5.w, a1.w);
            a2.x = fmaf(w6, v6.x, a2.x); a2.y = fmaf(w6, v6.y, a2.y);
            a2.z = fmaf(w6, v6.z, a2.z); a2.w = fmaf(w6, v6.w, a2.w);
            a3.x = fmaf(w7, v7.x, a3.x); a3.y = fmaf(w7, v7.y, a3.y);
            a3.z = fmaf(w7, v7.z, a3.z); a3.w = fmaf(w7, v7.w, a3.w);
        }
        for (; j < end; j++) {
            int2 e = g_csr[j];
            float4 v = ((const float4*)g_xw)[(size_t)e.x * 32 + lane];
            float w = __int_as_float(e.y);
            a0.x = fmaf(w, v.x, a0.x); a0.y = fmaf(w, v.y, a0.y);
            a0.z = fmaf(w, v.z, a0.z); a0.w = fmaf(w, v.w, a0.w);
        }
        a0.x = (a0.x + a1.x) + (a2.x + a3.x);
        a0.y = (a0.y + a1.y) + (a2.y + a3.y);
        a0.z = (a0.z + a1.z) + (a2.z + a3.z);
        a0.w = (a0.w + a1.w) + (a2.w + a3.w);
        ((float4*)g_h)[(size_t)n * 32 + lane] = a0;
    } else {
        a0 = make_float4(0.f, 0.f, 0.f, 0.f);
    }

    sh_s [warp][lane] = a0;
    sh_s2[warp][lane] = make_float4(a0.x * a0.x, a0.y * a0.y,
                                    a0.z * a0.z, a0.w * a0.w);
    __syncthreads();
    if (warp == 0) {
        float4 ts  = make_float4(0.f, 0.f, 0.f, 0.f);
        float4 ts2 = ts;
#pragma unroll
        for (int g = 0; g < 8; g++) {
            float4 s  = sh_s [g][lane];
            float4 s2 = sh_s2[g][lane];
            ts.x += s.x;  ts.y += s.y;  ts.z += s.z;  ts.w += s.w;
            ts2.x += s2.x; ts2.y += s2.y; ts2.z += s2.z; ts2.w += s2.w;
        }
        int slot = blockIdx.x & (STATS_B - 1);
        float* ps  = &g_psum  [slot][lane * 4];
        float* ps2 = &g_psumsq[slot][lane * 4];
        atomicAdd(ps + 0, ts.x);  atomicAdd(ps + 1, ts.y);
        atomicAdd(ps + 2, ts.z);  atomicAdd(ps + 3, ts.w);
        atomicAdd(ps2 + 0, ts2.x); atomicAdd(ps2 + 1, ts2.y);
        atomicAdd(ps2 + 2, ts2.z); atomicAdd(ps2 + 3, ts2.w);
    }
}

// layer 3: gather + bias + self-loop + log_softmax, one warp per node
__global__ void k_gather40_lsm(const float* __restrict__ b3,
                               float* __restrict__ out, int N) {
    int t = blockIdx.x * blockDim.x + threadIdx.x;
    int n = t >> 5, lane = t & 31;
    if (n >= N) return;
    float di = g_dinv[n]; di *= di;
    const float* xr = g_xw3 + (size_t)n * 40;
    float v1 = fmaf(di, xr[lane], b3[lane]);
    float v2 = (lane < 8) ? fmaf(di, xr[32 + lane], b3[32 + lane]) : 0.f;
    int j   = g_rowptr[n];
    int end = g_rowptr[n + 1];
    for (; j < end; j++) {
        int2 e = g_csr[j];
        float w = __int_as_float(e.y);
        const float* sr = g_xw3 + (size_t)e.x * 40;
        v1 = fmaf(w, sr[lane], v1);
        if (lane < 8) v2 = fmaf(w, sr[32 + lane], v2);
    }
    float m = (lane < 8) ? fmaxf(v1, v2) : v1;
#pragma unroll
    for (int o = 16; o > 0; o >>= 1) m = fmaxf(m, __shfl_xor_sync(0xffffffffu, m, o));
    float s = expf(v1 - m) + ((lane < 8) ? expf(v2 - m) : 0.f);
#pragma unroll
    for (int o = 16; o > 0; o >>= 1) s += __shfl_xor_sync(0xffffffffu, s, o);
    float l = m + logf(s);
    float* p = out + (size_t)n * 40;
    p[lane] = v1 - l;
    if (lane < 8) p[32 + lane] = v2 - l;
}

// ---------------- batch norm reduce (also re-zeroes partials) -----------------
__global__ void k_bn_reduce(const float* __restrict__ gamma,
                            const float* __restrict__ beta, float invN) {
    __shared__ float sh1[8][FDIM];
    __shared__ float sh2[8][FDIM];
    int col = threadIdx.x & 127;
    int grp = threadIdx.x >> 7;       // 0..7
    float s = 0.f, s2 = 0.f;
    for (int b = grp * (STATS_B / 8); b < (grp + 1) * (STATS_B / 8); b++) {
        s  += g_psum  [b][col];
        s2 += g_psumsq[b][col];
        g_psum  [b][col] = 0.f;
        g_psumsq[b][col] = 0.f;
    }
    sh1[grp][col] = s;
    sh2[grp][col] = s2;
    __syncthreads();
    if (grp == 0) {
        float ts = 0.f, ts2 = 0.f;
#pragma unroll
        for (int g = 0; g < 8; g++) { ts += sh1[g][col]; ts2 += sh2[g][col]; }
        float mean = ts * invN;
        float var  = fmaf(-mean, mean, ts2 * invN);
        float sc   = gamma[col] * rsqrtf(var + 1e-5f);
        g_scale[col] = sc;
        g_shift[col] = fmaf(-mean, sc, beta[col]);
    }
}

// ---------------- launch -----------------------------------------------------
extern "C" void kernel_launch(void* const* d_in, const int* in_sizes, int n_in,
                              void* d_out, int out_size) {
    const float* x   = (const float*)d_in[0];
    const int*   ei  = (const int*)d_in[1];     // int32 (JAX x64 disabled)
    const float* ew  = (const float*)d_in[2];
    const float* W1  = (const float*)d_in[3];
    const float* b1  = (const float*)d_in[4];
    const float* ga1 = (const float*)d_in[5];
    const float* be1 = (const float*)d_in[6];
    const float* W2  = (const float*)d_in[7];
    const float* b2  = (const float*)d_in[8];
    const float* ga2 = (const float*)d_in[9];
    const float* be2 = (const float*)d_in[10];
    const float* W3  = (const float*)d_in[11];
    const float* b3  = (const float*)d_in[12];
    float* out = (float*)d_out;

    int N = in_sizes[0] / FDIM;
    int E = in_sizes[2];

    const int TB = 256;
    int gbN  = (N + TB - 1) / TB;
    int gbE  = (E + TB - 1) / TB;
    int gbM  = (N + 127) / 128;
    int gbG  = (N + 7) / 8;                 // gather: 8 nodes / 256-thread block
    int gbNW = (N * 32 + TB - 1) / TB;      // warp-per-node

    // ---- prep + layer 1 GEMM interleaved ----
    // gemm1 depends only on (x, W1); placed at launch #4 so the profiler's
    // fixed capture slot finally lands on it.
    k_zero        <<<gbN, TB>>>(N);
    k_deg_cnt     <<<gbE, TB>>>(ei, ew, E, N);
    k_dinv        <<<gbN, TB>>>(N);
    k_gemm128_tf32<<<gbM, 256>>>(x, 0, W1, N);     // launch #4 (profiled)
    k_scan        <<<1, SCAN_T>>>(N);
    k_csr_build   <<<gbE, TB>>>(ei, ew, E, N);

    // ---- layer 1 aggregation + BN ----
    k_gather128<<<gbG, 256>>>(b1, N);
    k_bn_reduce<<<1, 1024>>>(ga1, be1, 1.0f / (float)N);

    // ---- layer 2 (BN1+relu fused into gemm A-load) ----
    k_gemm128_tf32<<<gbM, 256>>>(x, 1, W2, N);
    k_gather128   <<<gbG, 256>>>(b2, N);
    k_bn_reduce   <<<1, 1024>>>(ga2, be2, 1.0f / (float)N);

    // ---- layer 3 (BN2+relu fused) + log_softmax ----
    k_gemm40       <<<gbM, 256>>>(W3, N);
    k_gather40_lsm <<<gbNW, TB>>>(b3, out, N);
}

// round 12
// speedup vs baseline: 2.1291x; 1.0368x over previous
#include <cuda_runtime.h>
#include <cstdint>

#define NMAX 50000
#define EMAX 800000
#define FDIM 128
#define CDIM 40
#define SCAN_T 1024
#define STATS_B 512

// ---------------- device scratch (static allocation; no cudaMalloc) ----------
__device__ float g_xw [NMAX * FDIM];   // GEMM output of current layer
__device__ float g_h  [NMAX * FDIM];   // aggregated hidden state (pre-BN)
__device__ float g_xw3[NMAX * CDIM];   // layer-3 GEMM output
__device__ float g_deg [NMAX];         // edge-weight in-degree (without self loop)
__device__ float g_dinv[NMAX];
__device__ int   g_cnt   [NMAX];       // in-degree counts
__device__ int   g_rowptr[NMAX + 1];   // CSR row pointers (by dst)
__device__ int   g_cursor[NMAX];       // fill cursors
__device__ int2  g_csr   [EMAX];       // packed {src, bitcast(norm)}
__device__ float g_psum  [STATS_B][FDIM];   // BN partial sums   (zero-invariant:
__device__ float g_psumsq[STATS_B][FDIM];   //  bn_reduce re-zeroes after reading)
__device__ float g_scale[FDIM];
__device__ float g_shift[FDIM];

// ---------------- graph preprocessing ----------------------------------------
// edge_index is int32 (JAX x64 disabled downcasts jnp.int64 -> int32).
__global__ void k_zero(int N) {
    int i = blockIdx.x * blockDim.x + threadIdx.x;
    if (i < N) { g_deg[i] = 0.f; g_cnt[i] = 0; }
}

__global__ void k_deg_cnt(const int* __restrict__ ei,
                          const float* __restrict__ ew, int E, int N) {
    int e = blockIdx.x * blockDim.x + threadIdx.x;
    if (e >= E) return;
    int d = ei[E + e];
    if ((unsigned)d < (unsigned)N) {
        atomicAdd(&g_deg[d], ew[e]);
        atomicAdd(&g_cnt[d], 1);
    }
}

// grid-wide dinv
__global__ void k_dinv(int N) {
    int i = blockIdx.x * blockDim.x + threadIdx.x;
    if (i < N) g_dinv[i] = rsqrtf(g_deg[i] + 1.0f);   // +1 = self-loop weight
}

// single-block exclusive scan over counts -> rowptr + cursor
__global__ void k_scan(int N) {
    __shared__ int sh[SCAN_T];
    int tid = threadIdx.x;
    int chunk = (N + SCAN_T - 1) / SCAN_T;
    int start = tid * chunk;
    int end   = min(start + chunk, N);
    int sum = 0;
    for (int i = start; i < end; i++) sum += g_cnt[i];
    sh[tid] = sum;
    __syncthreads();
    for (int off = 1; off < SCAN_T; off <<= 1) {
        int v = (tid >= off) ? sh[tid - off] : 0;
        __syncthreads();
        sh[tid] += v;
        __syncthreads();
    }
    int off = sh[tid] - sum;   // exclusive prefix
    for (int i = start; i < end; i++) {
        g_rowptr[i] = off;
        g_cursor[i] = off;
        off += g_cnt[i];
    }
    if (tid == SCAN_T - 1) g_rowptr[N] = off;
}

// norm compute + CSR fill in one pass
__global__ void k_csr_build(const int* __restrict__ ei,
                            const float* __restrict__ ew, int E, int N) {
    int e = blockIdx.x * blockDim.x + threadIdx.x;
    if (e >= E) return;
    int s = ei[e];
    int d = ei[E + e];
    if ((unsigned)s >= (unsigned)N) s = 0;
    if ((unsigned)d >= (unsigned)N) d = 0;
    float nrm = g_dinv[s] * ew[e] * g_dinv[d];
    int pos = atomicAdd(&g_cursor[d], 1);
    g_csr[pos] = make_int2(s, __float_as_int(nrm));
}

// ---------------- split-precision TF32 helpers --------------------------------
__device__ __forceinline__ void split_tf32(float x, float& hi, float& lo) {
    uint32_t h;
    asm("cvt.rna.tf32.f32 %0, %1;" : "=r"(h) : "f"(x));
    hi = __uint_as_float(h);
    lo = x - hi;
}

__device__ __forceinline__ void mma_tf32(float* c, const uint32_t* a,
                                         uint32_t b0, uint32_t b1) {
    asm("mma.sync.aligned.m16n8k8.row.col.f32.tf32.tf32.f32 "
        "{%0,%1,%2,%3}, {%4,%5,%6,%7}, {%8,%9}, {%0,%1,%2,%3};"
        : "+f"(c[0]), "+f"(c[1]), "+f"(c[2]), "+f"(c[3])
        : "r"(a[0]), "r"(a[1]), "r"(a[2]), "r"(a[3]), "r"(b0), "r"(b1));
}

// ---------------- TF32 split GEMM: [M,128] @ [128,128] ------------------------
// D = A@B via (hi+lo) x (hi+lo), dropping lo*lo: fp32-class accuracy (~2^-21).
// __launch_bounds__(256, 2): regs capped to 128 so 2 CTAs/SM fit the RF.
// (R11 profile: 134 regs -> 1 CTA/SM, occ 12.2%, tensor pipe 30% idle-starved.)
#define KC 16
#define KPAD 17
__global__ __launch_bounds__(256, 2) void k_gemm128_tf32(const float* __restrict__ Aext,
                                                         int bnsel,
                                                         const float* __restrict__ B,
                                                         int M) {
    const float* __restrict__ A = bnsel ? (const float*)g_h : Aext;
    __shared__ float As_hi[128][KPAD];
    __shared__ float As_lo[128][KPAD];
    __shared__ float Bs_hi[128][KPAD];   // [n][k] (transposed on store)
    __shared__ float Bs_lo[128][KPAD];

    const int tid    = threadIdx.x;
    const int lane   = tid & 31;
    const int warp   = tid >> 5;
    const int warp_m = warp & 3;          // 4 x 32 rows
    const int warp_n = warp >> 2;         // 2 x 64 cols
    const int row0   = blockIdx.x * 128;

    // loader mapping (per 16-wide K chunk)
    const int a_row = tid >> 1;           // 0..127
    const int a_k0  = (tid & 1) * 8;      // two float4 = 8 k values
    const int b_k   = tid >> 4;           // 0..15
    const int b_n0  = (tid & 15) * 8;     // 8 n values (2 float4)

    float acc[2][8][4];
#pragma unroll
    for (int mt = 0; mt < 2; mt++)
#pragma unroll
        for (int nt = 0; nt < 8; nt++)
#pragma unroll
            for (int r = 0; r < 4; r++) acc[mt][nt][r] = 0.f;

#pragma unroll 1
    for (int ch = 0; ch < 128 / KC; ch++) {
        const int k0 = ch * KC;
        __syncthreads();   // protect smem from previous iteration's readers

        // ---- stage A chunk (with optional fused BN+ReLU), split hi/lo ----
        {
            int grow = row0 + a_row;
            float v[8];
#pragma unroll
            for (int i = 0; i < 8; i++) v[i] = 0.f;
            if (grow < M) {
                const float* ap = A + (size_t)grow * 128 + k0 + a_k0;
                float4 u0 = *(const float4*)ap;
                float4 u1 = *(const float4*)(ap + 4);
                v[0] = u0.x; v[1] = u0.y; v[2] = u0.z; v[3] = u0.w;
                v[4] = u1.x; v[5] = u1.y; v[6] = u1.z; v[7] = u1.w;
                if (bnsel) {
#pragma unroll
                    for (int i = 0; i < 8; i++) {
                        int c = k0 + a_k0 + i;
                        v[i] = fmaxf(0.f, fmaf(v[i], g_scale[c], g_shift[c]));
                    }
                }
            }
#pragma unroll
            for (int i = 0; i < 8; i++) {
                float hi, lo;
                split_tf32(v[i], hi, lo);
                As_hi[a_row][a_k0 + i] = hi;
                As_lo[a_row][a_k0 + i] = lo;
            }
        }
        // ---- stage B chunk transposed, split hi/lo ----
        {
            const float* bp = B + (size_t)(k0 + b_k) * 128 + b_n0;
            float4 u0 = *(const float4*)bp;
            float4 u1 = *(const float4*)(bp + 4);
            float v[8] = {u0.x, u0.y, u0.z, u0.w, u1.x, u1.y, u1.z, u1.w};
#pragma unroll
            for (int i = 0; i < 8; i++) {
                float hi, lo;
                split_tf32(v[i], hi, lo);
                Bs_hi[b_n0 + i][b_k] = hi;
                Bs_lo[b_n0 + i][b_k] = lo;
            }
        }
        __syncthreads();

        // ---- 2 k8 steps per chunk ----
#pragma unroll
        for (int s = 0; s < KC / 8; s++) {
            const int ac = s * 8 + (lane & 3);
            const int ar = warp_m * 32 + (lane >> 2);
            uint32_t a_hi[2][4], a_lo[2][4];
#pragma unroll
            for (int mt = 0; mt < 2; mt++) {
                int r = ar + mt * 16;
                a_hi[mt][0] = __float_as_uint(As_hi[r    ][ac    ]);
                a_hi[mt][1] = __float_as_uint(As_hi[r + 8][ac    ]);
                a_hi[mt][2] = __float_as_uint(As_hi[r    ][ac + 4]);
                a_hi[mt][3] = __float_as_uint(As_hi[r + 8][ac + 4]);
                a_lo[mt][0] = __float_as_uint(As_lo[r    ][ac    ]);
                a_lo[mt][1] = __float_as_uint(As_lo[r + 8][ac    ]);
                a_lo[mt][2] = __float_as_uint(As_lo[r    ][ac + 4]);
                a_lo[mt][3] = __float_as_uint(As_lo[r + 8][ac + 4]);
            }
            const int bk = s * 8 + (lane & 3);
#pragma unroll
            for (int nt = 0; nt < 8; nt++) {
                int bn = warp_n * 64 + nt * 8 + (lane >> 2);
                uint32_t bh0 = __float_as_uint(Bs_hi[bn][bk]);
                uint32_t bh1 = __float_as_uint(Bs_hi[bn][bk + 4]);
                uint32_t bl0 = __float_as_uint(Bs_lo[bn][bk]);
                uint32_t bl1 = __float_as_uint(Bs_lo[bn][bk + 4]);
#pragma unroll
                for (int mt = 0; mt < 2; mt++) {
                    mma_tf32(acc[mt][nt], a_hi[mt], bh0, bh1);
                    mma_tf32(acc[mt][nt], a_hi[mt], bl0, bl1);
                    mma_tf32(acc[mt][nt], a_lo[mt], bh0, bh1);
                }
            }
        }
    }

    // ---- epilogue: write g_xw ----
#pragma unroll
    for (int mt = 0; mt < 2; mt++) {
        int r0 = row0 + warp_m * 32 + mt * 16 + (lane >> 2);
        int r1 = r0 + 8;
#pragma unroll
        for (int nt = 0; nt < 8; nt++) {
            int col = warp_n * 64 + nt * 8 + (lane & 3) * 2;
            if (r0 < M)
                *(float2*)(g_xw + (size_t)r0 * 128 + col) =
                    make_float2(acc[mt][nt][0], acc[mt][nt][1]);
            if (r1 < M)
                *(float2*)(g_xw + (size_t)r1 * 128 + col) =
                    make_float2(acc[mt][nt][2], acc[mt][nt][3]);
        }
    }
}

// ---------------- SGEMM: [M,128] @ [128,40]  (BN2+relu(g_h) -> g_xw3) ---------
__global__ __launch_bounds__(256) void k_gemm40(const float* __restrict__ B,
                                                int M) {
    __shared__ float As[16][128];
    __shared__ float Bs[16][40];
    const int tid  = threadIdx.x;
    const int tx   = tid & 7;
    const int ty   = tid >> 3;
    const int row0 = blockIdx.x * 128;
    const int a_row = tid >> 1;
    const int a_k4  = (tid & 1) * 8;

    float acc[4][5];
#pragma unroll
    for (int i = 0; i < 4; i++)
#pragma unroll
        for (int j = 0; j < 5; j++) acc[i][j] = 0.f;

#pragma unroll 1
    for (int k0 = 0; k0 < 128; k0 += 16) {
        int grow = row0 + a_row;
        float4 av0 = make_float4(0.f, 0.f, 0.f, 0.f);
        float4 av1 = av0;
        if (grow < M) {
            const float* ap = g_h + (size_t)grow * 128 + k0 + a_k4;
            av0 = *(const float4*)ap;
            av1 = *(const float4*)(ap + 4);
            int c4 = (k0 + a_k4) >> 2;
            float4 sc0 = ((const float4*)g_scale)[c4];
            float4 sc1 = ((const float4*)g_scale)[c4 + 1];
            float4 sh0 = ((const float4*)g_shift)[c4];
            float4 sh1 = ((const float4*)g_shift)[c4 + 1];
            av0.x = fmaxf(0.f, fmaf(av0.x, sc0.x, sh0.x));
            av0.y = fmaxf(0.f, fmaf(av0.y, sc0.y, sh0.y));
            av0.z = fmaxf(0.f, fmaf(av0.z, sc0.z, sh0.z));
            av0.w = fmaxf(0.f, fmaf(av0.w, sc0.w, sh0.w));
            av1.x = fmaxf(0.f, fmaf(av1.x, sc1.x, sh1.x));
            av1.y = fmaxf(0.f, fmaf(av1.y, sc1.y, sh1.y));
            av1.z = fmaxf(0.f, fmaf(av1.z, sc1.z, sh1.z));
            av1.w = fmaxf(0.f, fmaf(av1.w, sc1.w, sh1.w));
        }
        As[a_k4 + 0][a_row] = av0.x; As[a_k4 + 1][a_row] = av0.y;
        As[a_k4 + 2][a_row] = av0.z; As[a_k4 + 3][a_row] = av0.w;
        As[a_k4 + 4][a_row] = av1.x; As[a_k4 + 5][a_row] = av1.y;
        As[a_k4 + 6][a_row] = av1.z; As[a_k4 + 7][a_row] = av1.w;

        for (int i = tid; i < 16 * 40; i += 256) {
            int bk = i / 40, bn = i % 40;
            Bs[bk][bn] = B[(size_t)(k0 + bk) * 40 + bn];
        }
        __syncthreads();

#pragma unroll
        for (int kk = 0; kk < 16; kk++) {
            float ar[4], br[5];
#pragma unroll
            for (int i = 0; i < 4; i++) ar[i] = As[kk][ty * 4 + i];
#pragma unroll
            for (int j = 0; j < 5; j++) br[j] = Bs[kk][tx * 5 + j];
#pragma unroll
            for (int i = 0; i < 4; i++)
#pragma unroll
                for (int j = 0; j < 5; j++)
                    acc[i][j] = fmaf(ar[i], br[j], acc[i][j]);
        }
        __syncthreads();
    }

#pragma unroll
    for (int i = 0; i < 4; i++) {
        int r = row0 + ty * 4 + i;
        if (r < M) {
#pragma unroll
            for (int j = 0; j < 5; j++)
                g_xw3[(size_t)r * 40 + tx * 5 + j] = acc[i][j];
        }
    }
}

// ---------------- CSR gather + fused BN partial stats -------------------------
// 8-edge unroll: 8 float4 loads in flight per warp (MLP=8) against L2 latency.
__global__ __launch_bounds__(256) void k_gather128(const float* __restrict__ b,
                                                   int N) {
    __shared__ float4 sh_s [8][32];
    __shared__ float4 sh_s2[8][32];
    const int warp = threadIdx.x >> 5;
    const int lane = threadIdx.x & 31;
    const int n = blockIdx.x * 8 + warp;

    float4 a0 = make_float4(0.f, 0.f, 0.f, 0.f);
    float4 a1 = a0, a2 = a0, a3 = a0;

    if (n < N) {
        float di = g_dinv[n]; di *= di;
        float4 bv = ((const float4*)b)[lane];
        float4 xv = ((const float4*)g_xw)[(size_t)n * 32 + lane];
        a0.x = fmaf(di, xv.x, bv.x); a0.y = fmaf(di, xv.y, bv.y);
        a0.z = fmaf(di, xv.z, bv.z); a0.w = fmaf(di, xv.w, bv.w);

        int j   = g_rowptr[n];
        int end = g_rowptr[n + 1];
        for (; j + 7 < end; j += 8) {      // MLP=8
            int2 e0 = g_csr[j],     e1 = g_csr[j + 1];
            int2 e2 = g_csr[j + 2], e3 = g_csr[j + 3];
            int2 e4 = g_csr[j + 4], e5 = g_csr[j + 5];
            int2 e6 = g_csr[j + 6], e7 = g_csr[j + 7];
            float4 v0 = ((const float4*)g_xw)[(size_t)e0.x * 32 + lane];
            float4 v1 = ((const float4*)g_xw)[(size_t)e1.x * 32 + lane];
            float4 v2 = ((const float4*)g_xw)[(size_t)e2.x * 32 + lane];
            float4 v3 = ((const float4*)g_xw)[(size_t)e3.x * 32 + lane];
            float4 v4 = ((const float4*)g_xw)[(size_t)e4.x * 32 + lane];
            float4 v5 = ((const float4*)g_xw)[(size_t)e5.x * 32 + lane];
            float4 v6 = ((const float4*)g_xw)[(size_t)e6.x * 32 + lane];
            float4 v7 = ((const float4*)g_xw)[(size_t)e7.x * 32 + lane];
            float w0 = __int_as_float(e0.y), w1 = __int_as_float(e1.y);
            float w2 = __int_as_float(e2.y), w3 = __int_as_float(e3.y);
            float w4 = __int_as_float(e4.y), w5 = __int_as_float(e5.y);
            float w6 = __int_as_float(e6.y), w7 = __int_as_float(e7.y);
            a0.x = fmaf(w0, v0.x, a0.x); a0.y = fmaf(w0, v0.y, a0.y);
            a0.z = fmaf(w0, v0.z, a0.z); a0.w = fmaf(w0, v0.w, a0.w);
            a1.x = fmaf(w1, v1.x, a1.x); a1.y = fmaf(w1, v1.y, a1.y);
            a1.z = fmaf(w1, v1.z, a1.z); a1.w = fmaf(w1, v1.w, a1.w);
            a2.x = fmaf(w2, v2.x, a2.x); a2.y = fmaf(w2, v2.y, a2.y);
            a2.z = fmaf(w2, v2.z, a2.z); a2.w = fmaf(w2, v2.w, a2.w);
            a3.x = fmaf(w3, v3.x, a3.x); a3.y = fmaf(w3, v3.y, a3.y);
            a3.z = fmaf(w3, v3.z, a3.z); a3.w = fmaf(w3, v3.w, a3.w);
            a0.x = fmaf(w4, v4.x, a0.x); a0.y = fmaf(w4, v4.y, a0.y);
            a0.z = fmaf(w4, v4.z, a0.z); a0.w = fmaf(w4, v4.w, a0.w);
            a1.x = fmaf(w5, v5.x, a1.x); a1.y = fmaf(w5, v5.y, a1.y);
            a1.z = fmaf(w5, v5.z, a1.z); a1.w = fmaf(w5, v5.w, a1.w);
            a2.x = fmaf(w6, v6.x, a2.x); a2.y = fmaf(w6, v6.y, a2.y);
            a2.z = fmaf(w6, v6.z, a2.z); a2.w = fmaf(w6, v6.w, a2.w);
            a3.x = fmaf(w7, v7.x, a3.x); a3.y = fmaf(w7, v7.y, a3.y);
            a3.z = fmaf(w7, v7.z, a3.z); a3.w = fmaf(w7, v7.w, a3.w);
        }
        for (; j < end; j++) {
            int2 e = g_csr[j];
            float4 v = ((const float4*)g_xw)[(size_t)e.x * 32 + lane];
            float w = __int_as_float(e.y);
            a0.x = fmaf(w, v.x, a0.x); a0.y = fmaf(w, v.y, a0.y);
            a0.z = fmaf(w, v.z, a0.z); a0.w = fmaf(w, v.w, a0.w);
        }
        a0.x = (a0.x + a1.x) + (a2.x + a3.x);
        a0.y = (a0.y + a1.y) + (a2.y + a3.y);
        a0.z = (a0.z + a1.z) + (a2.z + a3.z);
        a0.w = (a0.w + a1.w) + (a2.w + a3.w);
        ((float4*)g_h)[(size_t)n * 32 + lane] = a0;
    } else {
        a0 = make_float4(0.f, 0.f, 0.f, 0.f);
    }

    sh_s [warp][lane] = a0;
    sh_s2[warp][lane] = make_float4(a0.x * a0.x, a0.y * a0.y,
                                    a0.z * a0.z, a0.w * a0.w);
    __syncthreads();
    if (warp == 0) {
        float4 ts  = make_float4(0.f, 0.f, 0.f, 0.f);
        float4 ts2 = ts;
#pragma unroll
        for (int g = 0; g < 8; g++) {
            float4 s  = sh_s [g][lane];
            float4 s2 = sh_s2[g][lane];
            ts.x += s.x;  ts.y += s.y;  ts.z += s.z;  ts.w += s.w;
            ts2.x += s2.x; ts2.y += s2.y; ts2.z += s2.z; ts2.w += s2.w;
        }
        int slot = blockIdx.x & (STATS_B - 1);
        float* ps  = &g_psum  [slot][lane * 4];
        float* ps2 = &g_psumsq[slot][lane * 4];
        atomicAdd(ps + 0, ts.x);  atomicAdd(ps + 1, ts.y);
        atomicAdd(ps + 2, ts.z);  atomicAdd(ps + 3, ts.w);
        atomicAdd(ps2 + 0, ts2.x); atomicAdd(ps2 + 1, ts2.y);
        atomicAdd(ps2 + 2, ts2.z); atomicAdd(ps2 + 3, ts2.w);
    }
}

// layer 3: gather + bias + self-loop + log_softmax, one warp per node
__global__ void k_gather40_lsm(const float* __restrict__ b3,
                               float* __restrict__ out, int N) {
    int t = blockIdx.x * blockDim.x + threadIdx.x;
    int n = t >> 5, lane = t & 31;
    if (n >= N) return;
    float di = g_dinv[n]; di *= di;
    const float* xr = g_xw3 + (size_t)n * 40;
    float v1 = fmaf(di, xr[lane], b3[lane]);
    float v2 = (lane < 8) ? fmaf(di, xr[32 + lane], b3[32 + lane]) : 0.f;
    int j   = g_rowptr[n];
    int end = g_rowptr[n + 1];
    for (; j < end; j++) {
        int2 e = g_csr[j];
        float w = __int_as_float(e.y);
        const float* sr = g_xw3 + (size_t)e.x * 40;
        v1 = fmaf(w, sr[lane], v1);
        if (lane < 8) v2 = fmaf(w, sr[32 + lane], v2);
    }
    float m = (lane < 8) ? fmaxf(v1, v2) : v1;
#pragma unroll
    for (int o = 16; o > 0; o >>= 1) m = fmaxf(m, __shfl_xor_sync(0xffffffffu, m, o));
    float s = expf(v1 - m) + ((lane < 8) ? expf(v2 - m) : 0.f);
#pragma unroll
    for (int o = 16; o > 0; o >>= 1) s += __shfl_xor_sync(0xffffffffu, s, o);
    float l = m + logf(s);
    float* p = out + (size_t)n * 40;
    p[lane] = v1 - l;
    if (lane < 8) p[32 + lane] = v2 - l;
}

// ---------------- batch norm reduce (also re-zeroes partials) -----------------
__global__ void k_bn_reduce(const float* __restrict__ gamma,
                            const float* __restrict__ beta, float invN) {
    __shared__ float sh1[8][FDIM];
    __shared__ float sh2[8][FDIM];
    int col = threadIdx.x & 127;
    int grp = threadIdx.x >> 7;       // 0..7
    float s = 0.f, s2 = 0.f;
    for (int b = grp * (STATS_B / 8); b < (grp + 1) * (STATS_B / 8); b++) {
        s  += g_psum  [b][col];
        s2 += g_psumsq[b][col];
        g_psum  [b][col] = 0.f;
        g_psumsq[b][col] = 0.f;
    }
    sh1[grp][col] = s;
    sh2[grp][col] = s2;
    __syncthreads();
    if (grp == 0) {
        float ts = 0.f, ts2 = 0.f;
#pragma unroll
        for (int g = 0; g < 8; g++) { ts += sh1[g][col]; ts2 += sh2[g][col]; }
        float mean = ts * invN;
        float var  = fmaf(-mean, mean, ts2 * invN);
        float sc   = gamma[col] * rsqrtf(var + 1e-5f);
        g_scale[col] = sc;
        g_shift[col] = fmaf(-mean, sc, beta[col]);
    }
}

// ---------------- launch -----------------------------------------------------
extern "C" void kernel_launch(void* const* d_in, const int* in_sizes, int n_in,
                              void* d_out, int out_size) {
    const float* x   = (const float*)d_in[0];
    const int*   ei  = (const int*)d_in[1];     // int32 (JAX x64 disabled)
    const float* ew  = (const float*)d_in[2];
    const float* W1  = (const float*)d_in[3];
    const float* b1  = (const float*)d_in[4];
    const float* ga1 = (const float*)d_in[5];
    const float* be1 = (const float*)d_in[6];
    const float* W2  = (const float*)d_in[7];
    const float* b2  = (const float*)d_in[8];
    const float* ga2 = (const float*)d_in[9];
    const float* be2 = (const float*)d_in[10];
    const float* W3  = (const float*)d_in[11];
    const float* b3  = (const float*)d_in[12];
    float* out = (float*)d_out;

    int N = in_sizes[0] / FDIM;
    int E = in_sizes[2];

    const int TB = 256;
    int gbN  = (N + TB - 1) / TB;
    int gbE  = (E + TB - 1) / TB;
    int gbM  = (N + 127) / 128;
    int gbG  = (N + 7) / 8;                 // gather: 8 nodes / 256-thread block
    int gbNW = (N * 32 + TB - 1) / TB;      // warp-per-node

    // ---- prep + layer 1 GEMM interleaved (gemm1 at launch #4 for profiling) --
    k_zero        <<<gbN, TB>>>(N);
    k_deg_cnt     <<<gbE, TB>>>(ei, ew, E, N);
    k_dinv        <<<gbN, TB>>>(N);
    k_gemm128_tf32<<<gbM, 256>>>(x, 0, W1, N);     // launch #4 (profiled)
    k_scan        <<<1, SCAN_T>>>(N);
    k_csr_build   <<<gbE, TB>>>(ei, ew, E, N);

    // ---- layer 1 aggregation + BN ----
    k_gather128<<<gbG, 256>>>(b1, N);
    k_bn_reduce<<<1, 1024>>>(ga1, be1, 1.0f / (float)N);

    // ---- layer 2 (BN1+relu fused into gemm A-load) ----
    k_gemm128_tf32<<<gbM, 256>>>(x, 1, W2, N);
    k_gather128   <<<gbG, 256>>>(b2, N);
    k_bn_reduce   <<<1, 1024>>>(ga2, be2, 1.0f / (float)N);

    // ---- layer 3 (BN2+relu fused) + log_softmax ----
    k_gemm40       <<<gbM, 256>>>(W3, N);
    k_gather40_lsm <<<gbNW, TB>>>(b3, out, N);
}